// round 2
// baseline (speedup 1.0000x reference)
#include <cuda_runtime.h>
#include <math.h>

#define NROW   8
#define DCOLS  2097152
#define DD1    2048
#define DD2    1024
#define NBATCH 512

// ---------------- scratch (static device globals; no allocations) ----------
__device__ float         g_vsum[NROW * DCOLS];      // 64 MB working vsum
__device__ unsigned      g_minkey, g_maxkey;
__device__ float         g_s[3];                     // s0, s1=s0/5, s2=s1/17
__device__ float         g_dmax[2];
__device__ int           g_counts[2][128];
__device__ int           g_rank_lut[128];
__device__ float         g_msp_tab[7 * 128];         // [row][rank-col]
__device__ unsigned char g_rs_tab[128];              // bit i = scheme row i

// ---------------- helpers ---------------------------------------------------
__device__ __forceinline__ unsigned fencode(float f) {
    unsigned u = __float_as_uint(f);
    unsigned m = (unsigned)((int)u >> 31);
    return u ^ (m | 0x80000000u);
}
__device__ __forceinline__ float fdecode(unsigned k) {
    unsigned u = (k & 0x80000000u) ? (k ^ 0x80000000u) : ~k;
    return __uint_as_float(u);
}
__device__ __forceinline__ float sigm(float x) {
    return __fdiv_rn(1.0f, 1.0f + expf(-x));
}
// ste_floor exactly as the reference writes it
__device__ __forceinline__ float ste_floor(float x) {
    return x + (floorf(x) - x);
}

// Load column j of res = U - vsum, stable-sort (value, origIdx) ascending.
// u64 keys: orderable-float high 32, index low bits -> unique keys ->
// the sorting network reproduces jnp.argsort(kind='stable') exactly.
__device__ __forceinline__ void load_sort(const float* __restrict__ U, int j,
                                          float sv[8], int idx[8]) {
    unsigned long long key[8];
#pragma unroll
    for (int i = 0; i < 8; i++) {
        float r = U[(size_t)i * DCOLS + j] - g_vsum[(size_t)i * DCOLS + j];
        unsigned u = __float_as_uint(r);
        unsigned m = (unsigned)((int)u >> 31);
        u = u ^ (m | 0x80000000u);
        key[i] = ((unsigned long long)u << 32) | (unsigned)i;
    }
#pragma unroll
    for (int i = 1; i < 8; i++) {
#pragma unroll
        for (int k = i; k > 0; k--) {
            unsigned long long a = key[k - 1], b = key[k];
            bool sw = b < a;
            key[k - 1] = sw ? b : a;
            key[k]     = sw ? a : b;
        }
    }
#pragma unroll
    for (int i = 0; i < 8; i++) {
        unsigned u = (unsigned)(key[i] >> 32);
        u = (u & 0x80000000u) ? (u ^ 0x80000000u) : ~u;
        sv[i] = __uint_as_float(u);
        idx[i] = (int)(key[i] & 7u);
    }
}

__device__ __forceinline__ int column_code(const float sv[8], float dmax, float thr) {
    int code = 0;
#pragma unroll
    for (int i = 0; i < 7; i++) {
        float d  = sv[i + 1] - sv[i];
        float z  = __fdiv_rn(__fdiv_rn(d, dmax) - thr, 0.01f);
        float mv = sigm(z);
        code = (code << 1) | (int)rintf(mv);   // round half-to-even, matches jnp.round
    }
    return code;
}

// packed fp32 FMA (Blackwell f32x2 pipe — 2x scalar FFMA throughput)
__device__ __forceinline__ float2 ffma2(float2 a, float2 b, float2 c) {
    unsigned long long ua = *reinterpret_cast<unsigned long long*>(&a);
    unsigned long long ub = *reinterpret_cast<unsigned long long*>(&b);
    unsigned long long uc = *reinterpret_cast<unsigned long long*>(&c);
    unsigned long long ud;
    asm("fma.rn.f32x2 %0, %1, %2, %3;" : "=l"(ud) : "l"(ua), "l"(ub), "l"(uc));
    return *reinterpret_cast<float2*>(&ud);
}

// ---------------- kernels ---------------------------------------------------
__global__ void k_init() {
    int t = threadIdx.x;
    if (t < 128) { g_counts[0][t] = 0; g_counts[1][t] = 0; }
    if (t == 0) {
        g_minkey = 0xFFFFFFFFu;
        g_maxkey = 0u;
        g_dmax[0] = 0.0f;
        g_dmax[1] = 0.0f;
    }
}

__global__ void __launch_bounds__(256) k_minmax(const float* __restrict__ U) {
    float lmin = 3.4e38f, lmax = -3.4e38f;
    int stride = gridDim.x * blockDim.x;
    const float4* U4 = (const float4*)U;
    for (int i = blockIdx.x * blockDim.x + threadIdx.x; i < (NROW * DCOLS) / 4; i += stride) {
        float4 v = U4[i];
        lmin = fminf(lmin, fminf(fminf(v.x, v.y), fminf(v.z, v.w)));
        lmax = fmaxf(lmax, fmaxf(fmaxf(v.x, v.y), fmaxf(v.z, v.w)));
    }
#pragma unroll
    for (int o = 16; o; o >>= 1) {
        lmin = fminf(lmin, __shfl_xor_sync(0xffffffffu, lmin, o));
        lmax = fmaxf(lmax, __shfl_xor_sync(0xffffffffu, lmax, o));
    }
    __shared__ float smn[8], smx[8];
    int w = threadIdx.x >> 5;
    if ((threadIdx.x & 31) == 0) { smn[w] = lmin; smx[w] = lmax; }
    __syncthreads();
    if (threadIdx.x == 0) {
        float a = smn[0], b = smx[0];
        for (int q = 1; q < 8; q++) { a = fminf(a, smn[q]); b = fmaxf(b, smx[q]); }
        atomicMin(&g_minkey, fencode(a));
        atomicMax(&g_maxkey, fencode(b));
    }
}

__global__ void k_scales() {
    float mn = fdecode(g_minkey);
    float mx = fdecode(g_maxkey);
    float s0 = __fdiv_rn(mx - mn, 3.0f);
    g_s[0] = s0;
    float s1 = __fdiv_rn(s0, 5.0f);
    g_s[1] = s1;
    g_s[2] = __fdiv_rn(s1, 17.0f);
}

__global__ void __launch_bounds__(256) k_vsum_init(const float* __restrict__ U) {
    int i = blockIdx.x * 256 + threadIdx.x;
    float s = g_s[0];
    float v = U[i];
    float q = __fdiv_rn(v, s);
    g_vsum[i] = s * ste_floor(q);
}

__global__ void __launch_bounds__(256) k_deltamax(const float* __restrict__ U, int lvl) {
    int j = blockIdx.x * 256 + threadIdx.x;
    float sv[8]; int idx[8];
    load_sort(U, j, sv, idx);
    float m = 0.0f;
#pragma unroll
    for (int i = 0; i < 7; i++) m = fmaxf(m, sv[i + 1] - sv[i]);
#pragma unroll
    for (int o = 16; o; o >>= 1) m = fmaxf(m, __shfl_xor_sync(0xffffffffu, m, o));
    __shared__ float sm[8];
    int w = threadIdx.x >> 5;
    if ((threadIdx.x & 31) == 0) sm[w] = m;
    __syncthreads();
    if (threadIdx.x == 0) {
        float mm = sm[0];
        for (int q = 1; q < 8; q++) mm = fmaxf(mm, sm[q]);
        atomicMax((int*)&g_dmax[lvl], __float_as_int(mm));  // all deltas >= 0
    }
}

__global__ void __launch_bounds__(256) k_hist(const float* __restrict__ U,
                                              const float* __restrict__ tm, int lvl) {
    __shared__ int h[128];
    if (threadIdx.x < 128) h[threadIdx.x] = 0;
    __syncthreads();
    int j = blockIdx.x * 256 + threadIdx.x;
    float sv[8]; int idx[8];
    load_sort(U, j, sv, idx);
    float dmax = g_dmax[lvl];
    float thr  = sigm(tm[j >> 11]);           // repeat(thres_mean, D1) -> index j/2048
    int code = column_code(sv, dmax, thr);
    atomicAdd(&h[code], 1);
    __syncthreads();
    if (threadIdx.x < 128 && h[threadIdx.x])
        atomicAdd(&g_counts[lvl][threadIdx.x], h[threadIdx.x]);
}

__global__ void __launch_bounds__(128) k_finalize(const float* __restrict__ U,
                                                  const float* __restrict__ tm, int lvl) {
    __shared__ int cnts[128], rnk[128], tcode[5], trank[5];
    int p = threadIdx.x;
    cnts[p] = g_counts[lvl][p];
    __syncthreads();
    if (p == 0) {
        int r = 0;
        for (int q = 0; q < 128; q++) { rnk[q] = r; if (cnts[q] > 0) r++; }
        bool used[128];
        for (int q = 0; q < 128; q++) used[q] = false;
        for (int t = 0; t < 5; t++) {          // stable argsort(-counts)[:5]
            int best = -1, bc = -1;
            for (int q = 0; q < 128; q++)
                if (!used[q] && cnts[q] > bc) { bc = cnts[q]; best = q; }
            used[best] = true;
            tcode[t] = best;
            trank[t] = rnk[best];
        }
    }
    __syncthreads();

    // reassignment LUT: patterns @ patterns[top].T == popcount(p & top)
    int bestT = 0, bestV = -1;
#pragma unroll
    for (int t = 0; t < 5; t++) {
        int iv = __popc(p & tcode[t]);
        if (iv > bestV) { bestV = iv; bestT = t; }   // first max
    }
    bool istop = false;
#pragma unroll
    for (int t = 0; t < 5; t++) istop |= (rnk[p] == trank[t]);
    g_rank_lut[p] = istop ? rnk[p] : trank[bestT];

    // msp / rs table for columns 0..127 (the only columns c_rank can select)
    float sv[8]; int idx[8];
    load_sort(U, p, sv, idx);
    float dmax = g_dmax[lvl];
    float thr  = sigm(tm[p >> 11]);
    unsigned char bits = 0;
#pragma unroll
    for (int i = 0; i < 7; i++) {
        float d  = sv[i + 1] - sv[i];
        float z  = __fdiv_rn(__fdiv_rn(d, dmax) - thr, 0.01f);
        float mv = sigm(z);
        g_msp_tab[i * 128 + p] = mv;
        if ((int)rintf(mv)) bits |= (unsigned char)(1u << i);
    }
    g_rs_tab[p] = bits;
}

__global__ void __launch_bounds__(256) k_update(const float* __restrict__ U,
                                                const float* __restrict__ tm, int lvl) {
    int j = blockIdx.x * 256 + threadIdx.x;
    float sv[8]; int idx[8];
    load_sort(U, j, sv, idx);
    float dmax = g_dmax[lvl];
    float thr  = sigm(tm[j >> 11]);
    int code = column_code(sv, dmax, thr);

    int cr = g_rank_lut[code];
    unsigned sb = g_rs_tab[cr];
    float s = g_s[1 + lvl];

    // segmented mean scan (forward), exactly the reference recurrence
    float buf = 0.0f, cnt = 0.0f, g = 1.0f;
    bool reset = false;
    float v[8]; unsigned bl = 0;
#pragma unroll
    for (int i = 0; i < 8; i++) {
        if (reset) { buf = sv[i]; cnt = 1.0f; g = 1.0f; }
        else       { buf += sv[i]; cnt += 1.0f; }
        float mean = __fdiv_rn(buf, cnt);
        if (i == 7) {
            v[7] = g * mean;
        } else {
            bool b = (sb >> i) & 1u;
            float mu = g_msp_tab[i * 128 + cr];
            v[i] = b ? (g * mu) * mean : 0.0f;
            if (b) bl |= (1u << i);
            else   g = g * (1.0f - mu);
            reset = b;
        }
    }
    // backward segment fill
    float ro[8];
    float cur = v[7];
    ro[7] = cur;
#pragma unroll
    for (int i = 6; i >= 0; i--) {
        if ((bl >> i) & 1u) cur = v[i];
        ro[i] = cur;
    }
    // inverse permutation + quantized update (branchless select keeps regs)
#pragma unroll
    for (int i = 0; i < 8; i++) {
        float gi = 0.0f;
#pragma unroll
        for (int k = 0; k < 8; k++) gi = (idx[k] == i) ? ro[k] : gi;
        float q = __fdiv_rn(gi, s);
        g_vsum[(size_t)i * DCOLS + j] += s * ste_floor(q);
    }
}

// ---------------- GEMM: out[b,n,l] = sum_d x[b,n,d] * vsum[n, d*1024 + l] ---
// 128x128 tile, BK=16, 256 threads, 8x8 micro-tile via packed f32x2 FMA.
__global__ void __launch_bounds__(256, 2) k_gemm(const float* __restrict__ x,
                                                 float* __restrict__ out) {
    __shared__ __align__(16) float As[2][16][132];   // [k][m], padded
    __shared__ __align__(16) float Bs[2][16][128];   // [k][n]

    int tid = threadIdx.x;
    int n  = blockIdx.z;
    int bm = blockIdx.y * 128;
    int bn = blockIdx.x * 128;

    int arow = tid >> 2;           // 0..63 (and +64)
    int acol = (tid & 3) << 2;     // k within tile: 0,4,8,12
    int brow = tid >> 5;           // 0..7 (and +8)
    int bcol = (tid & 31) << 2;    // 0..124

    const float* Abase = x + (size_t)n * 2048 + (size_t)(bm + arow) * 16384 + acol;
    const float* Bbase = g_vsum + (size_t)n * (size_t)(2048 * 1024)
                                + (size_t)brow * 1024 + bn + bcol;

    int ty = tid >> 4, tx = tid & 15;
    int mrow = ty * 8, ncol = tx * 8;

    float2 acc[8][4];
#pragma unroll
    for (int i = 0; i < 8; i++)
#pragma unroll
        for (int p = 0; p < 4; p++) acc[i][p] = make_float2(0.0f, 0.0f);

    float4 ra0, ra1, rb0, rb1;
    // prologue: tile 0
    ra0 = *(const float4*)(Abase);
    ra1 = *(const float4*)(Abase + 64 * 16384);
    rb0 = *(const float4*)(Bbase);
    rb1 = *(const float4*)(Bbase + 8 * 1024);
    As[0][acol + 0][arow] = ra0.x; As[0][acol + 1][arow] = ra0.y;
    As[0][acol + 2][arow] = ra0.z; As[0][acol + 3][arow] = ra0.w;
    As[0][acol + 0][arow + 64] = ra1.x; As[0][acol + 1][arow + 64] = ra1.y;
    As[0][acol + 2][arow + 64] = ra1.z; As[0][acol + 3][arow + 64] = ra1.w;
    *(float4*)&Bs[0][brow][bcol]     = rb0;
    *(float4*)&Bs[0][brow + 8][bcol] = rb1;
    __syncthreads();

#pragma unroll 1
    for (int t = 0; t < 128; ++t) {
        int s = t & 1;
        if (t + 1 < 128) {
            int k0 = (t + 1) * 16;
            ra0 = *(const float4*)(Abase + k0);
            ra1 = *(const float4*)(Abase + 64 * 16384 + k0);
            rb0 = *(const float4*)(Bbase + (size_t)k0 * 1024);
            rb1 = *(const float4*)(Bbase + (size_t)(k0 + 8) * 1024);
        }
#pragma unroll
        for (int k = 0; k < 16; k++) {
            float4 a0 = *(const float4*)&As[s][k][mrow];
            float4 a1 = *(const float4*)&As[s][k][mrow + 4];
            float4 b0 = *(const float4*)&Bs[s][k][ncol];
            float4 b1 = *(const float4*)&Bs[s][k][ncol + 4];
            float av[8] = {a0.x, a0.y, a0.z, a0.w, a1.x, a1.y, a1.z, a1.w};
            float2 bv[4] = {make_float2(b0.x, b0.y), make_float2(b0.z, b0.w),
                            make_float2(b1.x, b1.y), make_float2(b1.z, b1.w)};
#pragma unroll
            for (int i = 0; i < 8; i++) {
                float2 ad = make_float2(av[i], av[i]);
#pragma unroll
                for (int p = 0; p < 4; p++) acc[i][p] = ffma2(ad, bv[p], acc[i][p]);
            }
        }
        if (t + 1 < 128) {
            int sn = s ^ 1;
            As[sn][acol + 0][arow] = ra0.x; As[sn][acol + 1][arow] = ra0.y;
            As[sn][acol + 2][arow] = ra0.z; As[sn][acol + 3][arow] = ra0.w;
            As[sn][acol + 0][arow + 64] = ra1.x; As[sn][acol + 1][arow + 64] = ra1.y;
            As[sn][acol + 2][arow + 64] = ra1.z; As[sn][acol + 3][arow + 64] = ra1.w;
            *(float4*)&Bs[sn][brow][bcol]     = rb0;
            *(float4*)&Bs[sn][brow + 8][bcol] = rb1;
            __syncthreads();
        }
    }

#pragma unroll
    for (int i = 0; i < 8; i++) {
        size_t off = (size_t)(bm + mrow + i) * 8192 + (size_t)n * 1024 + bn + ncol;
        float4 o0 = make_float4(acc[i][0].x, acc[i][0].y, acc[i][1].x, acc[i][1].y);
        float4 o1 = make_float4(acc[i][2].x, acc[i][2].y, acc[i][3].x, acc[i][3].y);
        *(float4*)(out + off)     = o0;
        *(float4*)(out + off + 4) = o1;
    }
}

// ---------------- launch ----------------------------------------------------
extern "C" void kernel_launch(void* const* d_in, const int* in_sizes, int n_in,
                              void* d_out, int out_size) {
    const float* x  = nullptr;
    const float* U  = nullptr;
    const float* tm = nullptr;
    for (int i = 0; i < n_in; i++) {
        if (in_sizes[i] == NROW * DCOLS)            U  = (const float*)d_in[i];
        else if (in_sizes[i] == NBATCH * NROW * DD1) x = (const float*)d_in[i];
        else if (in_sizes[i] == DD2)                 tm = (const float*)d_in[i];
    }
    float* out = (float*)d_out;

    k_init<<<1, 256>>>();
    k_minmax<<<2048, 256>>>(U);
    k_scales<<<1, 1>>>();
    k_vsum_init<<<(NROW * DCOLS) / 256, 256>>>(U);

    for (int lvl = 0; lvl < 2; lvl++) {
        k_deltamax<<<DCOLS / 256, 256>>>(U, lvl);
        k_hist<<<DCOLS / 256, 256>>>(U, tm, lvl);
        k_finalize<<<1, 128>>>(U, tm, lvl);
        k_update<<<DCOLS / 256, 256>>>(U, tm, lvl);
    }

    dim3 g(DD2 / 128, NBATCH / 128, NROW);
    k_gemm<<<g, 256>>>(x, out);
}

// round 4
// speedup vs baseline: 1.6301x; 1.6301x over previous
#include <cuda_runtime.h>
#include <cuda_bf16.h>
#include <math.h>
#include <stdint.h>

#define NROW   8
#define DCOLS  2097152
#define DD1    2048
#define DD2    1024
#define NBATCH 512
#define XELEMS (NBATCH * NROW * DD1)   // 8388608

// ---------------- scratch (static device globals; no allocations) ----------
__device__ float         g_vsum[NROW * DCOLS];                 // 64 MB (vsum1, then final W)
__device__ __nv_bfloat16 g_wthi[NROW * DCOLS];                 // 32 MB  W^T hi  [e][l][d1]
__device__ __nv_bfloat16 g_wtlo[NROW * DCOLS];                 // 32 MB  W^T lo
__device__ __nv_bfloat16 g_xhi[XELEMS];                        // 16 MB
__device__ __nv_bfloat16 g_xlo[XELEMS];                        // 16 MB
__device__ unsigned      g_minkey, g_maxkey;
__device__ float         g_s[3];
__device__ float         g_dmax[2];
__device__ int           g_counts[2][128];
__device__ int           g_rank_lut[128];
__device__ float         g_msp_tab[7 * 128];
__device__ unsigned char g_rs_tab[128];

// ---------------- helpers ---------------------------------------------------
__device__ __forceinline__ unsigned fencode(float f) {
    unsigned u = __float_as_uint(f);
    unsigned m = (unsigned)((int)u >> 31);
    return u ^ (m | 0x80000000u);
}
__device__ __forceinline__ float fdecode(unsigned k) {
    unsigned u = (k & 0x80000000u) ? (k ^ 0x80000000u) : ~k;
    return __uint_as_float(u);
}
__device__ __forceinline__ float sigm(float x) {
    return __fdiv_rn(1.0f, 1.0f + expf(-x));
}
__device__ __forceinline__ float ste_floor(float x) {
    return x + (floorf(x) - x);
}

// residual loaders (bit-identical to reference recomputation)
__device__ __forceinline__ void load_res_l0(const float* __restrict__ U, int j,
                                            float s0, float r[8]) {
#pragma unroll
    for (int i = 0; i < 8; i++) {
        float u = U[(size_t)i * DCOLS + j];
        float v = s0 * ste_floor(__fdiv_rn(u, s0));
        r[i] = u - v;
    }
}
__device__ __forceinline__ void load_res_l1(const float* __restrict__ U, int j, float r[8]) {
#pragma unroll
    for (int i = 0; i < 8; i++)
        r[i] = U[(size_t)i * DCOLS + j] - g_vsum[(size_t)i * DCOLS + j];
}

// Batcher 19-CE sorting network for 8 elements
#define SORT8(T, a)                                                     \
    {                                                                   \
        const int P[19][2] = {{0,1},{2,3},{4,5},{6,7},{0,2},{1,3},{4,6},\
            {5,7},{1,2},{5,6},{0,4},{3,7},{1,5},{2,6},{1,4},{3,6},      \
            {2,4},{3,5},{3,4}};                                         \
        _Pragma("unroll")                                               \
        for (int _p = 0; _p < 19; _p++) {                               \
            T _x = a[P[_p][0]], _y = a[P[_p][1]];                       \
            bool _sw = _y < _x;                                         \
            a[P[_p][0]] = _sw ? _y : _x;                                \
            a[P[_p][1]] = _sw ? _x : _y;                                \
        }                                                               \
    }

__device__ __forceinline__ void sort_vals(float r[8], float sv[8]) {
    unsigned k[8];
#pragma unroll
    for (int i = 0; i < 8; i++) k[i] = fencode(r[i]);
    SORT8(unsigned, k);
#pragma unroll
    for (int i = 0; i < 8; i++) sv[i] = fdecode(k[i]);
}
__device__ __forceinline__ void sort_idx(const float r[8], float sv[8], int idx[8]) {
    unsigned long long k[8];
#pragma unroll
    for (int i = 0; i < 8; i++)
        k[i] = ((unsigned long long)fencode(r[i]) << 32) | (unsigned)i;
    SORT8(unsigned long long, k);
#pragma unroll
    for (int i = 0; i < 8; i++) {
        sv[i] = fdecode((unsigned)(k[i] >> 32));
        idx[i] = (int)(k[i] & 7u);
    }
}

__device__ __forceinline__ int column_code(const float sv[8], float dmax, float thr) {
    int code = 0;
#pragma unroll
    for (int i = 0; i < 7; i++) {
        float d  = sv[i + 1] - sv[i];
        float z  = __fdiv_rn(__fdiv_rn(d, dmax) - thr, 0.01f);
        code = (code << 1) | (int)rintf(sigm(z));
    }
    return code;
}

// ---------------- PTX helpers (generic sm_80/90 features only) --------------
__device__ __forceinline__ uint32_t smem_u32(const void* p) {
    uint32_t a;
    asm("{ .reg .u64 t; cvta.to.shared.u64 t, %1; cvt.u32.u64 %0, t; }" : "=r"(a) : "l"(p));
    return a;
}
#define CP_ASYNC16(dst, src) \
    asm volatile("cp.async.cg.shared.global [%0], [%1], 16;" :: "r"(dst), "l"(src))
#define CP_COMMIT() asm volatile("cp.async.commit_group;" ::: "memory")
#define CP_WAIT(n)  asm volatile("cp.async.wait_group %0;" :: "n"(n) : "memory")
#define SWZ128(b)   ((b) ^ (((b) >> 3) & 0x70))

__device__ __forceinline__ void ldsm_x4(uint32_t& r0, uint32_t& r1, uint32_t& r2,
                                        uint32_t& r3, uint32_t addr) {
    asm volatile("ldmatrix.sync.aligned.m8n8.x4.shared.b16 {%0,%1,%2,%3}, [%4];"
                 : "=r"(r0), "=r"(r1), "=r"(r2), "=r"(r3) : "r"(addr));
}
__device__ __forceinline__ void ldsm_x2(uint32_t& r0, uint32_t& r1, uint32_t addr) {
    asm volatile("ldmatrix.sync.aligned.m8n8.x2.shared.b16 {%0,%1}, [%2];"
                 : "=r"(r0), "=r"(r1) : "r"(addr));
}
__device__ __forceinline__ void mma16816(float* c, const uint32_t* a, const uint32_t* b) {
    asm volatile("mma.sync.aligned.m16n8k16.row.col.f32.bf16.bf16.f32 "
                 "{%0,%1,%2,%3}, {%4,%5,%6,%7}, {%8,%9}, {%0,%1,%2,%3};"
                 : "+f"(c[0]), "+f"(c[1]), "+f"(c[2]), "+f"(c[3])
                 : "r"(a[0]), "r"(a[1]), "r"(a[2]), "r"(a[3]), "r"(b[0]), "r"(b[1]));
}

// ---------------- quant kernels ---------------------------------------------
__global__ void k_init() {
    int t = threadIdx.x;
    if (t < 128) { g_counts[0][t] = 0; g_counts[1][t] = 0; }
    if (t == 0) {
        g_minkey = 0xFFFFFFFFu; g_maxkey = 0u;
        g_dmax[0] = 0.0f; g_dmax[1] = 0.0f;
    }
}

__global__ void __launch_bounds__(256) k_minmax(const float* __restrict__ U) {
    float lmin = 3.4e38f, lmax = -3.4e38f;
    int stride = gridDim.x * blockDim.x;
    const float4* U4 = (const float4*)U;
    for (int i = blockIdx.x * blockDim.x + threadIdx.x; i < (NROW * DCOLS) / 4; i += stride) {
        float4 v = U4[i];
        lmin = fminf(lmin, fminf(fminf(v.x, v.y), fminf(v.z, v.w)));
        lmax = fmaxf(lmax, fmaxf(fmaxf(v.x, v.y), fmaxf(v.z, v.w)));
    }
#pragma unroll
    for (int o = 16; o; o >>= 1) {
        lmin = fminf(lmin, __shfl_xor_sync(0xffffffffu, lmin, o));
        lmax = fmaxf(lmax, __shfl_xor_sync(0xffffffffu, lmax, o));
    }
    __shared__ float smn[8], smx[8];
    int w = threadIdx.x >> 5;
    if ((threadIdx.x & 31) == 0) { smn[w] = lmin; smx[w] = lmax; }
    __syncthreads();
    if (threadIdx.x == 0) {
        float a = smn[0], b = smx[0];
        for (int q = 1; q < 8; q++) { a = fminf(a, smn[q]); b = fmaxf(b, smx[q]); }
        atomicMin(&g_minkey, fencode(a));
        atomicMax(&g_maxkey, fencode(b));
    }
}

__global__ void k_scales() {
    float mn = fdecode(g_minkey), mx = fdecode(g_maxkey);
    float s0 = __fdiv_rn(mx - mn, 3.0f);
    g_s[0] = s0;
    float s1 = __fdiv_rn(s0, 5.0f);
    g_s[1] = s1;
    g_s[2] = __fdiv_rn(s1, 17.0f);
}

__global__ void __launch_bounds__(256) k_xsplit(const float* __restrict__ x) {
    int v = blockIdx.x * 256 + threadIdx.x;                // float4 index
    float4 a = ((const float4*)x)[v];
    __nv_bfloat16 h0 = __float2bfloat16(a.x), h1 = __float2bfloat16(a.y);
    __nv_bfloat16 h2 = __float2bfloat16(a.z), h3 = __float2bfloat16(a.w);
    __nv_bfloat16 l0 = __float2bfloat16(a.x - __bfloat162float(h0));
    __nv_bfloat16 l1 = __float2bfloat16(a.y - __bfloat162float(h1));
    __nv_bfloat16 l2 = __float2bfloat16(a.z - __bfloat162float(h2));
    __nv_bfloat16 l3 = __float2bfloat16(a.w - __bfloat162float(h3));
    uint2 ph, pl;
    ph.x = ((uint32_t)__bfloat16_as_ushort(h1) << 16) | __bfloat16_as_ushort(h0);
    ph.y = ((uint32_t)__bfloat16_as_ushort(h3) << 16) | __bfloat16_as_ushort(h2);
    pl.x = ((uint32_t)__bfloat16_as_ushort(l1) << 16) | __bfloat16_as_ushort(l0);
    pl.y = ((uint32_t)__bfloat16_as_ushort(l3) << 16) | __bfloat16_as_ushort(l2);
    *(uint2*)(&g_xhi[(size_t)v * 4]) = ph;
    *(uint2*)(&g_xlo[(size_t)v * 4]) = pl;
}

__global__ void __launch_bounds__(256) k_deltamax0(const float* __restrict__ U) {
    int j = blockIdx.x * 256 + threadIdx.x;
    float r[8], sv[8];
    load_res_l0(U, j, g_s[0], r);
    sort_vals(r, sv);
    float m = 0.0f;
#pragma unroll
    for (int i = 0; i < 7; i++) m = fmaxf(m, sv[i + 1] - sv[i]);
#pragma unroll
    for (int o = 16; o; o >>= 1) m = fmaxf(m, __shfl_xor_sync(0xffffffffu, m, o));
    __shared__ float sm[8];
    int w = threadIdx.x >> 5;
    if ((threadIdx.x & 31) == 0) sm[w] = m;
    __syncthreads();
    if (threadIdx.x == 0) {
        float mm = sm[0];
        for (int q = 1; q < 8; q++) mm = fmaxf(mm, sm[q]);
        atomicMax((int*)&g_dmax[0], __float_as_int(mm));
    }
}

__global__ void __launch_bounds__(256) k_hist(const float* __restrict__ U,
                                              const float* __restrict__ tm, int lvl) {
    __shared__ int h[128];
    if (threadIdx.x < 128) h[threadIdx.x] = 0;
    __syncthreads();
    int j = blockIdx.x * 256 + threadIdx.x;
    float r[8], sv[8];
    if (lvl == 0) load_res_l0(U, j, g_s[0], r);
    else          load_res_l1(U, j, r);
    sort_vals(r, sv);
    float dmax = g_dmax[lvl];
    float thr  = sigm(tm[j >> 11]);
    atomicAdd(&h[column_code(sv, dmax, thr)], 1);
    __syncthreads();
    if (threadIdx.x < 128 && h[threadIdx.x])
        atomicAdd(&g_counts[lvl][threadIdx.x], h[threadIdx.x]);
}

__global__ void __launch_bounds__(128) k_finalize(const float* __restrict__ U,
                                                  const float* __restrict__ tm, int lvl) {
    __shared__ int cnts[128], rnk[128], tcode[5], trank[5];
    int p = threadIdx.x;
    cnts[p] = g_counts[lvl][p];
    __syncthreads();
    if (p == 0) {
        int r = 0;
        for (int q = 0; q < 128; q++) { rnk[q] = r; if (cnts[q] > 0) r++; }
        bool used[128];
        for (int q = 0; q < 128; q++) used[q] = false;
        for (int t = 0; t < 5; t++) {
            int best = -1, bc = -1;
            for (int q = 0; q < 128; q++)
                if (!used[q] && cnts[q] > bc) { bc = cnts[q]; best = q; }
            used[best] = true;
            tcode[t] = best; trank[t] = rnk[best];
        }
    }
    __syncthreads();
    int bestT = 0, bestV = -1;
#pragma unroll
    for (int t = 0; t < 5; t++) {
        int iv = __popc(p & tcode[t]);
        if (iv > bestV) { bestV = iv; bestT = t; }
    }
    bool istop = false;
#pragma unroll
    for (int t = 0; t < 5; t++) istop |= (rnk[p] == trank[t]);
    g_rank_lut[p] = istop ? rnk[p] : trank[bestT];

    float r[8], sv[8];
    if (lvl == 0) load_res_l0(U, p, g_s[0], r);
    else          load_res_l1(U, p, r);
    sort_vals(r, sv);
    float dmax = g_dmax[lvl];
    float thr  = sigm(tm[p >> 11]);
    unsigned char bits = 0;
#pragma unroll
    for (int i = 0; i < 7; i++) {
        float d  = sv[i + 1] - sv[i];
        float z  = __fdiv_rn(__fdiv_rn(d, dmax) - thr, 0.01f);
        float mv = sigm(z);
        g_msp_tab[i * 128 + p] = mv;
        if ((int)rintf(mv)) bits |= (unsigned char)(1u << i);
    }
    g_rs_tab[p] = bits;
}

// update level `lvl`; lvl 0 additionally computes deltamax for level 1 (fused)
__global__ void __launch_bounds__(256) k_update(const float* __restrict__ U,
                                                const float* __restrict__ tm, int lvl) {
    int j = blockIdx.x * 256 + threadIdx.x;
    float uv[8], vs[8], r[8];
    float s0 = g_s[0];
#pragma unroll
    for (int i = 0; i < 8; i++) {
        uv[i] = U[(size_t)i * DCOLS + j];
        vs[i] = (lvl == 0) ? s0 * ste_floor(__fdiv_rn(uv[i], s0))
                           : g_vsum[(size_t)i * DCOLS + j];
        r[i] = uv[i] - vs[i];
    }
    float sv[8]; int idx[8];
    sort_idx(r, sv, idx);
    float dmax = g_dmax[lvl];
    float thr  = sigm(tm[j >> 11]);
    int code = column_code(sv, dmax, thr);
    int cr = g_rank_lut[code];
    unsigned sb = g_rs_tab[cr];
    float s = g_s[1 + lvl];

    float buf = 0.0f, cnt = 0.0f, g = 1.0f;
    bool reset = false;
    float v[8]; unsigned bl = 0;
#pragma unroll
    for (int i = 0; i < 8; i++) {
        if (reset) { buf = sv[i]; cnt = 1.0f; g = 1.0f; }
        else       { buf += sv[i]; cnt += 1.0f; }
        float mean = __fdiv_rn(buf, cnt);
        if (i == 7) v[7] = g * mean;
        else {
            bool b = (sb >> i) & 1u;
            float mu = g_msp_tab[i * 128 + cr];
            v[i] = b ? (g * mu) * mean : 0.0f;
            if (b) bl |= (1u << i);
            else   g = g * (1.0f - mu);
            reset = b;
        }
    }
    float ro[8];
    float cur = v[7];
    ro[7] = cur;
#pragma unroll
    for (int i = 6; i >= 0; i--) {
        if ((bl >> i) & 1u) cur = v[i];
        ro[i] = cur;
    }
    float nv[8];
#pragma unroll
    for (int i = 0; i < 8; i++) {
        float gi = 0.0f;
#pragma unroll
        for (int k = 0; k < 8; k++) gi = (idx[k] == i) ? ro[k] : gi;
        nv[i] = vs[i] + s * ste_floor(__fdiv_rn(gi, s));
        g_vsum[(size_t)i * DCOLS + j] = nv[i];
    }
    if (lvl == 0) {
        float r1[8], s1[8];
#pragma unroll
        for (int i = 0; i < 8; i++) r1[i] = uv[i] - nv[i];
        sort_vals(r1, s1);
        float m = 0.0f;
#pragma unroll
        for (int i = 0; i < 7; i++) m = fmaxf(m, s1[i + 1] - s1[i]);
#pragma unroll
        for (int o = 16; o; o >>= 1) m = fmaxf(m, __shfl_xor_sync(0xffffffffu, m, o));
        __shared__ float sm[8];
        int w = threadIdx.x >> 5;
        if ((threadIdx.x & 31) == 0) sm[w] = m;
        __syncthreads();
        if (threadIdx.x == 0) {
            float mm = sm[0];
            for (int q = 1; q < 8; q++) mm = fmaxf(mm, sm[q]);
            atomicMax((int*)&g_dmax[1], __float_as_int(mm));
        }
    }
}

// transpose + bf16-split W: g_vsum [e][d1][d2] fp32 -> g_wthi/g_wtlo [e][d2][d1]
__global__ void __launch_bounds__(256) k_wtrans() {
    __shared__ float ts[64][65];
    int e = blockIdx.z;
    int d1_0 = blockIdx.y * 64;
    int d2_0 = blockIdx.x * 64;
    int tx = threadIdx.x & 15, ty = threadIdx.x >> 4;
#pragma unroll
    for (int i = 0; i < 4; i++) {
        int row = ty + 16 * i;
        float4 v = *(const float4*)(&g_vsum[(size_t)e * DCOLS + (size_t)(d1_0 + row) * 1024 + d2_0 + tx * 4]);
        ts[row][tx * 4 + 0] = v.x; ts[row][tx * 4 + 1] = v.y;
        ts[row][tx * 4 + 2] = v.z; ts[row][tx * 4 + 3] = v.w;
    }
    __syncthreads();
#pragma unroll
    for (int i = 0; i < 4; i++) {
        int row = ty + 16 * i;                 // d2 local
        float w0 = ts[tx * 4 + 0][row], w1 = ts[tx * 4 + 1][row];
        float w2 = ts[tx * 4 + 2][row], w3 = ts[tx * 4 + 3][row];
        __nv_bfloat16 h0 = __float2bfloat16(w0), h1 = __float2bfloat16(w1);
        __nv_bfloat16 h2 = __float2bfloat16(w2), h3 = __float2bfloat16(w3);
        __nv_bfloat16 l0 = __float2bfloat16(w0 - __bfloat162float(h0));
        __nv_bfloat16 l1 = __float2bfloat16(w1 - __bfloat162float(h1));
        __nv_bfloat16 l2 = __float2bfloat16(w2 - __bfloat162float(h2));
        __nv_bfloat16 l3 = __float2bfloat16(w3 - __bfloat162float(h3));
        uint2 ph, pl;
        ph.x = ((uint32_t)__bfloat16_as_ushort(h1) << 16) | __bfloat16_as_ushort(h0);
        ph.y = ((uint32_t)__bfloat16_as_ushort(h3) << 16) | __bfloat16_as_ushort(h2);
        pl.x = ((uint32_t)__bfloat16_as_ushort(l1) << 16) | __bfloat16_as_ushort(l0);
        pl.y = ((uint32_t)__bfloat16_as_ushort(l3) << 16) | __bfloat16_as_ushort(l2);
        size_t off = (size_t)e * DCOLS + (size_t)(d2_0 + row) * 2048 + d1_0 + tx * 4;
        *(uint2*)(&g_wthi[off]) = ph;
        *(uint2*)(&g_wtlo[off]) = pl;
    }
}

// ---------------- HMMA GEMM (mma.sync bf16, generic sm_103-legal) -----------
// out[b,e,l] = sum_k x[b,e,k] * w[e,k,l]
// A (m=b) K-major from g_xhi/g_xlo; B (n=l) K-major from g_wthi/g_wtlo.
// D = Ah*Bh + Ah*Bl + Al*Bh, fp32 accumulate in registers.
#define GEMM_SMEM (2 * 65536)

__global__ void __launch_bounds__(256, 1) k_gemm(float* __restrict__ out) {
    extern __shared__ char smemraw[];
    uint32_t smb = smem_u32(smemraw);
    int tid = threadIdx.x, wid = tid >> 5, lane = tid & 31;
    int e = blockIdx.z, bm = blockIdx.y * 128, bn = blockIdx.x * 128;

    const __nv_bfloat16* Ah = g_xhi  + (size_t)e * 2048  + (size_t)bm * 16384;
    const __nv_bfloat16* Al = g_xlo  + (size_t)e * 2048  + (size_t)bm * 16384;
    const __nv_bfloat16* Bh = g_wthi + (size_t)e * DCOLS + (size_t)bn * 2048;
    const __nv_bfloat16* Bl = g_wtlo + (size_t)e * DCOLS + (size_t)bn * 2048;

    // staging: stage layout  [Ah 16K][Al 16K][Bh 16K][Bl 16K], SW128 swizzle
    int srow = tid >> 3;               // shared by the 4 iters via +32 rows
    int sc8  = tid & 7;
    uint32_t swz[4];
    size_t aofs[4], bofs[4];
#pragma unroll
    for (int i = 0; i < 4; i++) {
        int row = srow + i * 32;
        swz[i]  = SWZ128((uint32_t)(row * 128 + sc8 * 16));
        aofs[i] = (size_t)row * 16384 + sc8 * 8;
        bofs[i] = (size_t)row * 2048  + sc8 * 8;
    }

    int wm = (wid & 1) * 64, wn = (wid >> 1) * 32;
    int a_row = lane & 15;
    int a_kb  = (lane >> 4) * 16;
    int b_row = lane & 7;
    int b_kb  = ((lane >> 3) & 1) * 16;

    float c[4][4][4];
#pragma unroll
    for (int mi = 0; mi < 4; mi++)
#pragma unroll
        for (int ni = 0; ni < 4; ni++)
#pragma unroll
            for (int q = 0; q < 4; q++) c[mi][ni][q] = 0.0f;

    // prologue: stage 0
    {
        uint32_t base = smb;
#pragma unroll
        for (int i = 0; i < 4; i++) {
            CP_ASYNC16(base + swz[i],         Ah + aofs[i]);
            CP_ASYNC16(base + 16384 + swz[i], Al + aofs[i]);
            CP_ASYNC16(base + 32768 + swz[i], Bh + bofs[i]);
            CP_ASYNC16(base + 49152 + swz[i], Bl + bofs[i]);
        }
        CP_COMMIT();
    }

#pragma unroll 1
    for (int t = 0; t < 32; t++) {
        if (t + 1 < 32) {
            uint32_t base = smb + ((t + 1) & 1) * 65536;
            int k0 = (t + 1) * 64;
#pragma unroll
            for (int i = 0; i < 4; i++) {
                CP_ASYNC16(base + swz[i],         Ah + aofs[i] + k0);
                CP_ASYNC16(base + 16384 + swz[i], Al + aofs[i] + k0);
                CP_ASYNC16(base + 32768 + swz[i], Bh + bofs[i] + k0);
                CP_ASYNC16(base + 49152 + swz[i], Bl + bofs[i] + k0);
            }
            CP_COMMIT();
            CP_WAIT(1);
        } else {
            CP_WAIT(0);
        }
        __syncthreads();

        uint32_t base = smb + (t & 1) * 65536;
#pragma unroll
        for (int ks = 0; ks < 4; ks++) {
            uint32_t ah[4][4], al[4][4], bh[4][2], bl[4][2];
#pragma unroll
            for (int mi = 0; mi < 4; mi++) {
                int row = wm + mi * 16 + a_row;
                uint32_t off = SWZ128((uint32_t)(row * 128 + ks * 32 + a_kb));
                ldsm_x4(ah[mi][0], ah[mi][1], ah[mi][2], ah[mi][3], base + off);
                ldsm_x4(al[mi][0], al[mi][1], al[mi][2], al[mi][3], base + 16384 + off);
            }
#pragma unroll
            for (int ni = 0; ni < 4; ni++) {
                int row = wn + ni * 8 + b_row;
                uint32_t off = SWZ128((uint32_t)(row * 128 + ks * 32 + b_kb));
                ldsm_x2(bh[ni][0], bh[ni][1], base + 32768 + off);
                ldsm_x2(bl[ni][0], bl[ni][1], base + 49152 + off);
            }
#pragma unroll
            for (int mi = 0; mi < 4; mi++)
#pragma unroll
                for (int ni = 0; ni < 4; ni++) {
                    mma16816(c[mi][ni], ah[mi], bh[ni]);
                    mma16816(c[mi][ni], ah[mi], bl[ni]);
                    mma16816(c[mi][ni], al[mi], bh[ni]);
                }
        }
        __syncthreads();
    }

    // epilogue
    int group = lane >> 2, tig = lane & 3;
#pragma unroll
    for (int mi = 0; mi < 4; mi++) {
        int m0 = bm + wm + mi * 16 + group;
#pragma unroll
        for (int ni = 0; ni < 4; ni++) {
            int n0 = bn + wn + ni * 8 + tig * 2;
            float2 v0 = make_float2(c[mi][ni][0], c[mi][ni][1]);
            float2 v1 = make_float2(c[mi][ni][2], c[mi][ni][3]);
            *(float2*)(out + (size_t)m0 * 8192 + (size_t)e * 1024 + n0)       = v0;
            *(float2*)(out + (size_t)(m0 + 8) * 8192 + (size_t)e * 1024 + n0) = v1;
        }
    }
}

// ---------------- launch ----------------------------------------------------
extern "C" void kernel_launch(void* const* d_in, const int* in_sizes, int n_in,
                              void* d_out, int out_size) {
    const float* x = nullptr; const float* U = nullptr; const float* tm = nullptr;
    for (int i = 0; i < n_in; i++) {
        if (in_sizes[i] == NROW * DCOLS)      U  = (const float*)d_in[i];
        else if (in_sizes[i] == XELEMS)       x  = (const float*)d_in[i];
        else if (in_sizes[i] == DD2)          tm = (const float*)d_in[i];
    }
    float* out = (float*)d_out;

    cudaFuncSetAttribute(k_gemm, cudaFuncAttributeMaxDynamicSharedMemorySize, GEMM_SMEM);

    k_init<<<1, 256>>>();
    k_minmax<<<2048, 256>>>(U);
    k_scales<<<1, 1>>>();
    k_xsplit<<<XELEMS / 1024, 256>>>(x);

    k_deltamax0<<<DCOLS / 256, 256>>>(U);
    k_hist<<<DCOLS / 256, 256>>>(U, tm, 0);
    k_finalize<<<1, 128>>>(U, tm, 0);
    k_update<<<DCOLS / 256, 256>>>(U, tm, 0);      // writes vsum1, fused deltamax1

    k_hist<<<DCOLS / 256, 256>>>(U, tm, 1);
    k_finalize<<<1, 128>>>(U, tm, 1);
    k_update<<<DCOLS / 256, 256>>>(U, tm, 1);      // writes final W into g_vsum

    dim3 gt(DD2 / 64, DD1 / 64, NROW);
    k_wtrans<<<gt, 256>>>();

    dim3 gg(DD2 / 128, NBATCH / 128, NROW);
    k_gemm<<<gg, 256, GEMM_SMEM>>>(out);
}

// round 5
// speedup vs baseline: 1.6960x; 1.0405x over previous
#include <cuda_runtime.h>
#include <cuda_bf16.h>
#include <math.h>
#include <stdint.h>

#define NROW   8
#define DCOLS  2097152
#define DD1    2048
#define DD2    1024
#define NBATCH 512
#define XELEMS (NBATCH * NROW * DD1)   // 8388608

// ---------------- scratch (static device globals; no allocations) ----------
__device__ float         g_vsum[NROW * DCOLS];   // 64 MB (vsum1 between levels)
__device__ __nv_bfloat16 g_whi[NROW * DCOLS];    // 32 MB  W hi, natural [e][k][n]
__device__ __nv_bfloat16 g_wlo[NROW * DCOLS];    // 32 MB  W lo
__device__ __nv_bfloat16 g_xhi[XELEMS];          // 16 MB
__device__ __nv_bfloat16 g_xlo[XELEMS];          // 16 MB
__device__ unsigned      g_minkey, g_maxkey;
__device__ float         g_s[3];
__device__ float         g_dmax[2];
__device__ int           g_counts[2][128];
__device__ int           g_rank_lut[128];
__device__ float         g_msp_tab[7 * 128];
__device__ unsigned char g_rs_tab[128];

// ---------------- helpers ---------------------------------------------------
__device__ __forceinline__ unsigned fencode(float f) {
    unsigned u = __float_as_uint(f);
    unsigned m = (unsigned)((int)u >> 31);
    return u ^ (m | 0x80000000u);
}
__device__ __forceinline__ float fdecode(unsigned k) {
    unsigned u = (k & 0x80000000u) ? (k ^ 0x80000000u) : ~k;
    return __uint_as_float(u);
}
__device__ __forceinline__ float sigm(float x) {
    return __fdiv_rn(1.0f, 1.0f + expf(-x));
}
__device__ __forceinline__ float ste_floor(float x) {
    return x + (floorf(x) - x);
}

__device__ __forceinline__ void load_res_l0(const float* __restrict__ U, int j,
                                            float s0, float r[8]) {
#pragma unroll
    for (int i = 0; i < 8; i++) {
        float u = U[(size_t)i * DCOLS + j];
        float v = s0 * ste_floor(__fdiv_rn(u, s0));
        r[i] = u - v;
    }
}
__device__ __forceinline__ void load_res_l1(const float* __restrict__ U, int j, float r[8]) {
#pragma unroll
    for (int i = 0; i < 8; i++)
        r[i] = U[(size_t)i * DCOLS + j] - g_vsum[(size_t)i * DCOLS + j];
}

// Batcher 19-CE sorting network for 8 elements
#define SORT8(T, a)                                                     \
    {                                                                   \
        const int P[19][2] = {{0,1},{2,3},{4,5},{6,7},{0,2},{1,3},{4,6},\
            {5,7},{1,2},{5,6},{0,4},{3,7},{1,5},{2,6},{1,4},{3,6},      \
            {2,4},{3,5},{3,4}};                                         \
        _Pragma("unroll")                                               \
        for (int _p = 0; _p < 19; _p++) {                               \
            T _x = a[P[_p][0]], _y = a[P[_p][1]];                       \
            bool _sw = _y < _x;                                         \
            a[P[_p][0]] = _sw ? _y : _x;                                \
            a[P[_p][1]] = _sw ? _x : _y;                                \
        }                                                               \
    }

__device__ __forceinline__ void sort_vals(float r[8], float sv[8]) {
    unsigned k[8];
#pragma unroll
    for (int i = 0; i < 8; i++) k[i] = fencode(r[i]);
    SORT8(unsigned, k);
#pragma unroll
    for (int i = 0; i < 8; i++) sv[i] = fdecode(k[i]);
}
__device__ __forceinline__ void sort_idx(const float r[8], float sv[8], int idx[8]) {
    unsigned long long k[8];
#pragma unroll
    for (int i = 0; i < 8; i++)
        k[i] = ((unsigned long long)fencode(r[i]) << 32) | (unsigned)i;
    SORT8(unsigned long long, k);
#pragma unroll
    for (int i = 0; i < 8; i++) {
        sv[i] = fdecode((unsigned)(k[i] >> 32));
        idx[i] = (int)(k[i] & 7u);
    }
}

__device__ __forceinline__ int column_code(const float sv[8], float dmax, float thr) {
    int code = 0;
#pragma unroll
    for (int i = 0; i < 7; i++) {
        float d  = sv[i + 1] - sv[i];
        float z  = __fdiv_rn(__fdiv_rn(d, dmax) - thr, 0.01f);
        code = (code << 1) | (int)rintf(sigm(z));
    }
    return code;
}

// ---------------- PTX helpers -------------------------------------------------
__device__ __forceinline__ uint32_t smem_u32(const void* p) {
    uint32_t a;
    asm("{ .reg .u64 t; cvta.to.shared.u64 t, %1; cvt.u32.u64 %0, t; }" : "=r"(a) : "l"(p));
    return a;
}
#define CP_ASYNC16(dst, src) \
    asm volatile("cp.async.cg.shared.global [%0], [%1], 16;" :: "r"(dst), "l"(src))
#define CP_COMMIT() asm volatile("cp.async.commit_group;" ::: "memory")
#define CP_WAIT(n)  asm volatile("cp.async.wait_group %0;" :: "n"(n) : "memory")
#define SWZ128(b)   ((b) ^ (((b) >> 3) & 0x70))

__device__ __forceinline__ void ldsm_x4(uint32_t& r0, uint32_t& r1, uint32_t& r2,
                                        uint32_t& r3, uint32_t addr) {
    asm volatile("ldmatrix.sync.aligned.m8n8.x4.shared.b16 {%0,%1,%2,%3}, [%4];"
                 : "=r"(r0), "=r"(r1), "=r"(r2), "=r"(r3) : "r"(addr));
}
__device__ __forceinline__ void ldsm_x4t(uint32_t& r0, uint32_t& r1, uint32_t& r2,
                                         uint32_t& r3, uint32_t addr) {
    asm volatile("ldmatrix.sync.aligned.m8n8.x4.trans.shared.b16 {%0,%1,%2,%3}, [%4];"
                 : "=r"(r0), "=r"(r1), "=r"(r2), "=r"(r3) : "r"(addr));
}
__device__ __forceinline__ void mma16816(float* c, const uint32_t* a, const uint32_t* b) {
    asm volatile("mma.sync.aligned.m16n8k16.row.col.f32.bf16.bf16.f32 "
                 "{%0,%1,%2,%3}, {%4,%5,%6,%7}, {%8,%9}, {%0,%1,%2,%3};"
                 : "+f"(c[0]), "+f"(c[1]), "+f"(c[2]), "+f"(c[3])
                 : "r"(a[0]), "r"(a[1]), "r"(a[2]), "r"(a[3]), "r"(b[0]), "r"(b[1]));
}

// ---------------- quant kernels ---------------------------------------------
__global__ void k_init() {
    int t = threadIdx.x;
    if (t < 128) { g_counts[0][t] = 0; g_counts[1][t] = 0; }
    if (t == 0) {
        g_minkey = 0xFFFFFFFFu; g_maxkey = 0u;
        g_dmax[0] = 0.0f; g_dmax[1] = 0.0f;
    }
}

__global__ void __launch_bounds__(256) k_minmax(const float* __restrict__ U) {
    float lmin = 3.4e38f, lmax = -3.4e38f;
    int stride = gridDim.x * blockDim.x;
    const float4* U4 = (const float4*)U;
    for (int i = blockIdx.x * blockDim.x + threadIdx.x; i < (NROW * DCOLS) / 4; i += stride) {
        float4 v = U4[i];
        lmin = fminf(lmin, fminf(fminf(v.x, v.y), fminf(v.z, v.w)));
        lmax = fmaxf(lmax, fmaxf(fmaxf(v.x, v.y), fmaxf(v.z, v.w)));
    }
#pragma unroll
    for (int o = 16; o; o >>= 1) {
        lmin = fminf(lmin, __shfl_xor_sync(0xffffffffu, lmin, o));
        lmax = fmaxf(lmax, __shfl_xor_sync(0xffffffffu, lmax, o));
    }
    __shared__ float smn[8], smx[8];
    int w = threadIdx.x >> 5;
    if ((threadIdx.x & 31) == 0) { smn[w] = lmin; smx[w] = lmax; }
    __syncthreads();
    if (threadIdx.x == 0) {
        float a = smn[0], b = smx[0];
        for (int q = 1; q < 8; q++) { a = fminf(a, smn[q]); b = fmaxf(b, smx[q]); }
        atomicMin(&g_minkey, fencode(a));
        atomicMax(&g_maxkey, fencode(b));
    }
}

__global__ void k_scales() {
    float mn = fdecode(g_minkey), mx = fdecode(g_maxkey);
    float s0 = __fdiv_rn(mx - mn, 3.0f);
    g_s[0] = s0;
    float s1 = __fdiv_rn(s0, 5.0f);
    g_s[1] = s1;
    g_s[2] = __fdiv_rn(s1, 17.0f);
}

__global__ void __launch_bounds__(256) k_xsplit(const float* __restrict__ x) {
    int v = blockIdx.x * 256 + threadIdx.x;
    float4 a = ((const float4*)x)[v];
    __nv_bfloat16 h0 = __float2bfloat16(a.x), h1 = __float2bfloat16(a.y);
    __nv_bfloat16 h2 = __float2bfloat16(a.z), h3 = __float2bfloat16(a.w);
    __nv_bfloat16 l0 = __float2bfloat16(a.x - __bfloat162float(h0));
    __nv_bfloat16 l1 = __float2bfloat16(a.y - __bfloat162float(h1));
    __nv_bfloat16 l2 = __float2bfloat16(a.z - __bfloat162float(h2));
    __nv_bfloat16 l3 = __float2bfloat16(a.w - __bfloat162float(h3));
    uint2 ph, pl;
    ph.x = ((uint32_t)__bfloat16_as_ushort(h1) << 16) | __bfloat16_as_ushort(h0);
    ph.y = ((uint32_t)__bfloat16_as_ushort(h3) << 16) | __bfloat16_as_ushort(h2);
    pl.x = ((uint32_t)__bfloat16_as_ushort(l1) << 16) | __bfloat16_as_ushort(l0);
    pl.y = ((uint32_t)__bfloat16_as_ushort(l3) << 16) | __bfloat16_as_ushort(l2);
    *(uint2*)(&g_xhi[(size_t)v * 4]) = ph;
    *(uint2*)(&g_xlo[(size_t)v * 4]) = pl;
}

__global__ void __launch_bounds__(256) k_deltamax0(const float* __restrict__ U) {
    int j = blockIdx.x * 256 + threadIdx.x;
    float r[8], sv[8];
    load_res_l0(U, j, g_s[0], r);
    sort_vals(r, sv);
    float m = 0.0f;
#pragma unroll
    for (int i = 0; i < 7; i++) m = fmaxf(m, sv[i + 1] - sv[i]);
#pragma unroll
    for (int o = 16; o; o >>= 1) m = fmaxf(m, __shfl_xor_sync(0xffffffffu, m, o));
    __shared__ float sm[8];
    int w = threadIdx.x >> 5;
    if ((threadIdx.x & 31) == 0) sm[w] = m;
    __syncthreads();
    if (threadIdx.x == 0) {
        float mm = sm[0];
        for (int q = 1; q < 8; q++) mm = fmaxf(mm, sm[q]);
        atomicMax((int*)&g_dmax[0], __float_as_int(mm));
    }
}

__global__ void __launch_bounds__(256) k_hist(const float* __restrict__ U,
                                              const float* __restrict__ tm, int lvl) {
    __shared__ int h[128];
    if (threadIdx.x < 128) h[threadIdx.x] = 0;
    __syncthreads();
    int j = blockIdx.x * 256 + threadIdx.x;
    float r[8], sv[8];
    if (lvl == 0) load_res_l0(U, j, g_s[0], r);
    else          load_res_l1(U, j, r);
    sort_vals(r, sv);
    float dmax = g_dmax[lvl];
    float thr  = sigm(tm[j >> 11]);
    atomicAdd(&h[column_code(sv, dmax, thr)], 1);
    __syncthreads();
    if (threadIdx.x < 128 && h[threadIdx.x])
        atomicAdd(&g_counts[lvl][threadIdx.x], h[threadIdx.x]);
}

__global__ void __launch_bounds__(128) k_finalize(const float* __restrict__ U,
                                                  const float* __restrict__ tm, int lvl) {
    __shared__ int cnts[128], rnk[128], tcode[5], trank[5];
    int p = threadIdx.x;
    cnts[p] = g_counts[lvl][p];
    __syncthreads();
    if (p == 0) {
        int r = 0;
        for (int q = 0; q < 128; q++) { rnk[q] = r; if (cnts[q] > 0) r++; }
        bool used[128];
        for (int q = 0; q < 128; q++) used[q] = false;
        for (int t = 0; t < 5; t++) {
            int best = -1, bc = -1;
            for (int q = 0; q < 128; q++)
                if (!used[q] && cnts[q] > bc) { bc = cnts[q]; best = q; }
            used[best] = true;
            tcode[t] = best; trank[t] = rnk[best];
        }
    }
    __syncthreads();
    int bestT = 0, bestV = -1;
#pragma unroll
    for (int t = 0; t < 5; t++) {
        int iv = __popc(p & tcode[t]);
        if (iv > bestV) { bestV = iv; bestT = t; }
    }
    bool istop = false;
#pragma unroll
    for (int t = 0; t < 5; t++) istop |= (rnk[p] == trank[t]);
    g_rank_lut[p] = istop ? rnk[p] : trank[bestT];

    float r[8], sv[8];
    if (lvl == 0) load_res_l0(U, p, g_s[0], r);
    else          load_res_l1(U, p, r);
    sort_vals(r, sv);
    float dmax = g_dmax[lvl];
    float thr  = sigm(tm[p >> 11]);
    unsigned char bits = 0;
#pragma unroll
    for (int i = 0; i < 7; i++) {
        float d  = sv[i + 1] - sv[i];
        float z  = __fdiv_rn(__fdiv_rn(d, dmax) - thr, 0.01f);
        float mv = sigm(z);
        g_msp_tab[i * 128 + p] = mv;
        if ((int)rintf(mv)) bits |= (unsigned char)(1u << i);
    }
    g_rs_tab[p] = bits;
}

// update level lvl; lvl0: writes vsum1 fp32 + fused deltamax1.
// lvl1: writes final W directly as bf16 hi/lo in natural [e][k][n] layout.
__global__ void __launch_bounds__(256) k_update(const float* __restrict__ U,
                                                const float* __restrict__ tm, int lvl) {
    int j = blockIdx.x * 256 + threadIdx.x;
    float uv[8], vs[8], r[8];
    float s0 = g_s[0];
#pragma unroll
    for (int i = 0; i < 8; i++) {
        uv[i] = U[(size_t)i * DCOLS + j];
        vs[i] = (lvl == 0) ? s0 * ste_floor(__fdiv_rn(uv[i], s0))
                           : g_vsum[(size_t)i * DCOLS + j];
        r[i] = uv[i] - vs[i];
    }
    float sv[8]; int idx[8];
    sort_idx(r, sv, idx);
    float dmax = g_dmax[lvl];
    float thr  = sigm(tm[j >> 11]);
    int code = column_code(sv, dmax, thr);
    int cr = g_rank_lut[code];
    unsigned sb = g_rs_tab[cr];
    float s = g_s[1 + lvl];

    float buf = 0.0f, cnt = 0.0f, g = 1.0f;
    bool reset = false;
    float v[8]; unsigned bl = 0;
#pragma unroll
    for (int i = 0; i < 8; i++) {
        if (reset) { buf = sv[i]; cnt = 1.0f; g = 1.0f; }
        else       { buf += sv[i]; cnt += 1.0f; }
        float mean = __fdiv_rn(buf, cnt);
        if (i == 7) v[7] = g * mean;
        else {
            bool b = (sb >> i) & 1u;
            float mu = g_msp_tab[i * 128 + cr];
            v[i] = b ? (g * mu) * mean : 0.0f;
            if (b) bl |= (1u << i);
            else   g = g * (1.0f - mu);
            reset = b;
        }
    }
    float ro[8];
    float cur = v[7];
    ro[7] = cur;
#pragma unroll
    for (int i = 6; i >= 0; i--) {
        if ((bl >> i) & 1u) cur = v[i];
        ro[i] = cur;
    }
    if (lvl == 0) {
        float nv[8];
#pragma unroll
        for (int i = 0; i < 8; i++) {
            float gi = 0.0f;
#pragma unroll
            for (int k = 0; k < 8; k++) gi = (idx[k] == i) ? ro[k] : gi;
            nv[i] = vs[i] + s * ste_floor(__fdiv_rn(gi, s));
            g_vsum[(size_t)i * DCOLS + j] = nv[i];
        }
        // fused deltamax for level 1
        float r1[8], s1[8];
#pragma unroll
        for (int i = 0; i < 8; i++) r1[i] = uv[i] - nv[i];
        sort_vals(r1, s1);
        float m = 0.0f;
#pragma unroll
        for (int i = 0; i < 7; i++) m = fmaxf(m, s1[i + 1] - s1[i]);
#pragma unroll
        for (int o = 16; o; o >>= 1) m = fmaxf(m, __shfl_xor_sync(0xffffffffu, m, o));
        __shared__ float sm[8];
        int w = threadIdx.x >> 5;
        if ((threadIdx.x & 31) == 0) sm[w] = m;
        __syncthreads();
        if (threadIdx.x == 0) {
            float mm = sm[0];
            for (int q = 1; q < 8; q++) mm = fmaxf(mm, sm[q]);
            atomicMax((int*)&g_dmax[1], __float_as_int(mm));
        }
    } else {
#pragma unroll
        for (int i = 0; i < 8; i++) {
            float gi = 0.0f;
#pragma unroll
            for (int k = 0; k < 8; k++) gi = (idx[k] == i) ? ro[k] : gi;
            float nv = vs[i] + s * ste_floor(__fdiv_rn(gi, s));
            __nv_bfloat16 hi = __float2bfloat16(nv);
            __nv_bfloat16 lo = __float2bfloat16(nv - __bfloat162float(hi));
            g_whi[(size_t)i * DCOLS + j] = hi;
            g_wlo[(size_t)i * DCOLS + j] = lo;
        }
    }
}

// ---------------- HMMA GEMM (3-stage cp.async, B via ldmatrix.trans) --------
// out[b,e,l] = sum_k x[b,e,k] * w[e,k,l]
// A K-major [m][k] from g_xhi/g_xlo; B natural [k][n] from g_whi/g_wlo.
// D = Ah*Bh + Ah*Bl + Al*Bh, fp32 accumulate.
// Stage (64KB): AH 16K @0, AL @16384, BH @32768, BL @49152. 3 stages.
#define GEMM_SMEM (3 * 65536)
#define BSWZ(k, cbyte) ((uint32_t)((k) * 256 + (cbyte)) ^ ((uint32_t)((k) & 7) << 4))

__global__ void __launch_bounds__(256, 1) k_gemm(float* __restrict__ out) {
    extern __shared__ char smemraw[];
    uint32_t smb = smem_u32(smemraw);
    int tid = threadIdx.x, wid = tid >> 5, lane = tid & 31;
    int e = blockIdx.z, bm = blockIdx.y * 128, bn = blockIdx.x * 128;

    const __nv_bfloat16* Ah = g_xhi + (size_t)e * 2048  + (size_t)bm * 16384;
    const __nv_bfloat16* Al = g_xlo + (size_t)e * 2048  + (size_t)bm * 16384;
    const __nv_bfloat16* Bh = g_whi + (size_t)e * DCOLS + bn;
    const __nv_bfloat16* Bl = g_wlo + (size_t)e * DCOLS + bn;

    // staging address precompute
    uint32_t aswz[4], bswz[4];
    size_t aofs[4], bofs[4];
#pragma unroll
    for (int i = 0; i < 4; i++) {
        int v = tid + i * 256;
        int arow = v >> 3, ac = v & 7;          // A: 128 rows x 8 chunks
        aswz[i] = SWZ128((uint32_t)(arow * 128 + ac * 16));
        aofs[i] = (size_t)arow * 16384 + ac * 8;
        int brow = v >> 4, bc = v & 15;         // B: 64 rows x 16 chunks
        bswz[i] = BSWZ(brow, bc * 16);
        bofs[i] = (size_t)brow * 1024 + bc * 8;
    }

    int wm = (wid & 1) * 64, wn = (wid >> 1) * 32;
    int a_row = lane & 15;
    int a_kb  = (lane >> 4) * 16;
    int b_krb = (lane & 7) + ((lane >> 3) & 1) * 8;   // k within 16
    int b_nch = (lane >> 4) * 8;                      // n half within 16

    float c[4][4][4];
#pragma unroll
    for (int mi = 0; mi < 4; mi++)
#pragma unroll
        for (int ni = 0; ni < 4; ni++)
#pragma unroll
            for (int q = 0; q < 4; q++) c[mi][ni][q] = 0.0f;

    // prologue: stages 0, 1
#pragma unroll
    for (int t = 0; t < 2; t++) {
        uint32_t base = smb + t * 65536;
        int k0 = t * 64;
#pragma unroll
        for (int i = 0; i < 4; i++) {
            CP_ASYNC16(base + aswz[i],         Ah + aofs[i] + k0);
            CP_ASYNC16(base + 16384 + aswz[i], Al + aofs[i] + k0);
            CP_ASYNC16(base + 32768 + bswz[i], Bh + bofs[i] + (size_t)k0 * 1024);
            CP_ASYNC16(base + 49152 + bswz[i], Bl + bofs[i] + (size_t)k0 * 1024);
        }
        CP_COMMIT();
    }

#pragma unroll 1
    for (int t = 0; t < 32; t++) {
        if (t == 31) { CP_WAIT(0); } else { CP_WAIT(1); }
        __syncthreads();
        if (t + 2 < 32) {
            uint32_t base = smb + ((t + 2) % 3) * 65536;
            int k0 = (t + 2) * 64;
#pragma unroll
            for (int i = 0; i < 4; i++) {
                CP_ASYNC16(base + aswz[i],         Ah + aofs[i] + k0);
                CP_ASYNC16(base + 16384 + aswz[i], Al + aofs[i] + k0);
                CP_ASYNC16(base + 32768 + bswz[i], Bh + bofs[i] + (size_t)k0 * 1024);
                CP_ASYNC16(base + 49152 + bswz[i], Bl + bofs[i] + (size_t)k0 * 1024);
            }
            CP_COMMIT();
        }

        uint32_t base = smb + (t % 3) * 65536;
#pragma unroll
        for (int ks = 0; ks < 4; ks++) {
            uint32_t ah[4][4], al[4][4], bh[4][2], blr[4][2];
#pragma unroll
            for (int mi = 0; mi < 4; mi++) {
                int row = wm + mi * 16 + a_row;
                uint32_t off = SWZ128((uint32_t)(row * 128 + ks * 32 + a_kb));
                ldsm_x4(ah[mi][0], ah[mi][1], ah[mi][2], ah[mi][3], base + off);
                ldsm_x4(al[mi][0], al[mi][1], al[mi][2], al[mi][3], base + 16384 + off);
            }
#pragma unroll
            for (int np = 0; np < 2; np++) {
                int k_row = ks * 16 + b_krb;
                int n_col = wn + np * 16 + b_nch;
                uint32_t off = BSWZ(k_row, (n_col >> 3) << 4);
                uint32_t r0, r1, r2, r3;
                ldsm_x4t(r0, r1, r2, r3, base + 32768 + off);
                bh[np * 2][0] = r0; bh[np * 2][1] = r1;
                bh[np * 2 + 1][0] = r2; bh[np * 2 + 1][1] = r3;
                ldsm_x4t(r0, r1, r2, r3, base + 49152 + off);
                blr[np * 2][0] = r0; blr[np * 2][1] = r1;
                blr[np * 2 + 1][0] = r2; blr[np * 2 + 1][1] = r3;
            }
#pragma unroll
            for (int mi = 0; mi < 4; mi++)
#pragma unroll
                for (int ni = 0; ni < 4; ni++) {
                    mma16816(c[mi][ni], ah[mi], bh[ni]);
                    mma16816(c[mi][ni], ah[mi], blr[ni]);
                    mma16816(c[mi][ni], al[mi], bh[ni]);
                }
        }
    }

    // epilogue
    int group = lane >> 2, tig = lane & 3;
#pragma unroll
    for (int mi = 0; mi < 4; mi++) {
        int m0 = bm + wm + mi * 16 + group;
#pragma unroll
        for (int ni = 0; ni < 4; ni++) {
            int n0 = bn + wn + ni * 8 + tig * 2;
            float2 v0 = make_float2(c[mi][ni][0], c[mi][ni][1]);
            float2 v1 = make_float2(c[mi][ni][2], c[mi][ni][3]);
            *(float2*)(out + (size_t)m0 * 8192 + (size_t)e * 1024 + n0)       = v0;
            *(float2*)(out + (size_t)(m0 + 8) * 8192 + (size_t)e * 1024 + n0) = v1;
        }
    }
}

// ---------------- launch ----------------------------------------------------
extern "C" void kernel_launch(void* const* d_in, const int* in_sizes, int n_in,
                              void* d_out, int out_size) {
    const float* x = nullptr; const float* U = nullptr; const float* tm = nullptr;
    for (int i = 0; i < n_in; i++) {
        if (in_sizes[i] == NROW * DCOLS)      U  = (const float*)d_in[i];
        else if (in_sizes[i] == XELEMS)       x  = (const float*)d_in[i];
        else if (in_sizes[i] == DD2)          tm = (const float*)d_in[i];
    }
    float* out = (float*)d_out;

    cudaFuncSetAttribute(k_gemm, cudaFuncAttributeMaxDynamicSharedMemorySize, GEMM_SMEM);

    k_init<<<1, 256>>>();
    k_minmax<<<2048, 256>>>(U);
    k_scales<<<1, 1>>>();
    k_xsplit<<<XELEMS / 1024, 256>>>(x);

    k_deltamax0<<<DCOLS / 256, 256>>>(U);
    k_hist<<<DCOLS / 256, 256>>>(U, tm, 0);
    k_finalize<<<1, 128>>>(U, tm, 0);
    k_update<<<DCOLS / 256, 256>>>(U, tm, 0);      // writes vsum1, fused deltamax1

    k_hist<<<DCOLS / 256, 256>>>(U, tm, 1);
    k_finalize<<<1, 128>>>(U, tm, 1);
    k_update<<<DCOLS / 256, 256>>>(U, tm, 1);      // writes W hi/lo bf16 directly

    dim3 gg(DD2 / 128, NBATCH / 128, NROW);
    k_gemm<<<gg, 256, GEMM_SMEM>>>(out);
}

// round 6
// speedup vs baseline: 2.0792x; 1.2259x over previous
#include <cuda_runtime.h>
#include <cuda_fp16.h>
#include <math.h>
#include <stdint.h>

#define NROW   8
#define DCOLS  2097152
#define DD1    2048
#define DD2    1024
#define NBATCH 512
#define XELEMS (NBATCH * NROW * DD1)   // 8388608

// ---------------- scratch (static device globals; no allocations) ----------
__device__ float         g_vsum[NROW * DCOLS];   // 64 MB (vsum1 between levels)
__device__ __half        g_wh[NROW * DCOLS];     // 16 MB  W fp16, natural [e][k][n]
__device__ __half        g_xh[XELEMS];           // 16 MB  x fp16
__device__ unsigned      g_minkey, g_maxkey;
__device__ float         g_s[3];
__device__ float         g_dmax[2];
__device__ int           g_counts[2][128];
__device__ int           g_rank_lut[128];
__device__ float         g_msp_tab[7 * 128];
__device__ unsigned char g_rs_tab[128];

// ---------------- helpers ---------------------------------------------------
__device__ __forceinline__ unsigned fencode(float f) {
    unsigned u = __float_as_uint(f);
    unsigned m = (unsigned)((int)u >> 31);
    return u ^ (m | 0x80000000u);
}
__device__ __forceinline__ float fdecode(unsigned k) {
    unsigned u = (k & 0x80000000u) ? (k ^ 0x80000000u) : ~k;
    return __uint_as_float(u);
}
__device__ __forceinline__ float sigm(float x) {
    return __fdiv_rn(1.0f, 1.0f + expf(-x));
}
__device__ __forceinline__ float ste_floor(float x) {
    return x + (floorf(x) - x);
}

__device__ __forceinline__ void load_res_l0(const float* __restrict__ U, int j,
                                            float s0, float r[8]) {
#pragma unroll
    for (int i = 0; i < 8; i++) {
        float u = U[(size_t)i * DCOLS + j];
        float v = s0 * ste_floor(__fdiv_rn(u, s0));
        r[i] = u - v;
    }
}
__device__ __forceinline__ void load_res_l1(const float* __restrict__ U, int j, float r[8]) {
#pragma unroll
    for (int i = 0; i < 8; i++)
        r[i] = U[(size_t)i * DCOLS + j] - g_vsum[(size_t)i * DCOLS + j];
}

// Batcher 19-CE sorting network for 8 elements
#define SORT8(T, a)                                                     \
    {                                                                   \
        const int P[19][2] = {{0,1},{2,3},{4,5},{6,7},{0,2},{1,3},{4,6},\
            {5,7},{1,2},{5,6},{0,4},{3,7},{1,5},{2,6},{1,4},{3,6},      \
            {2,4},{3,5},{3,4}};                                         \
        _Pragma("unroll")                                               \
        for (int _p = 0; _p < 19; _p++) {                               \
            T _x = a[P[_p][0]], _y = a[P[_p][1]];                       \
            bool _sw = _y < _x;                                         \
            a[P[_p][0]] = _sw ? _y : _x;                                \
            a[P[_p][1]] = _sw ? _x : _y;                                \
        }                                                               \
    }

__device__ __forceinline__ void sort_vals(float r[8], float sv[8]) {
    unsigned k[8];
#pragma unroll
    for (int i = 0; i < 8; i++) k[i] = fencode(r[i]);
    SORT8(unsigned, k);
#pragma unroll
    for (int i = 0; i < 8; i++) sv[i] = fdecode(k[i]);
}
__device__ __forceinline__ void sort_idx(const float r[8], float sv[8], int idx[8]) {
    unsigned long long k[8];
#pragma unroll
    for (int i = 0; i < 8; i++)
        k[i] = ((unsigned long long)fencode(r[i]) << 32) | (unsigned)i;
    SORT8(unsigned long long, k);
#pragma unroll
    for (int i = 0; i < 8; i++) {
        sv[i] = fdecode((unsigned)(k[i] >> 32));
        idx[i] = (int)(k[i] & 7u);
    }
}

__device__ __forceinline__ int column_code(const float sv[8], float dmax, float thr) {
    int code = 0;
#pragma unroll
    for (int i = 0; i < 7; i++) {
        float d  = sv[i + 1] - sv[i];
        float z  = __fdiv_rn(__fdiv_rn(d, dmax) - thr, 0.01f);
        code = (code << 1) | (int)rintf(sigm(z));
    }
    return code;
}

// ---------------- PTX helpers -------------------------------------------------
__device__ __forceinline__ uint32_t smem_u32(const void* p) {
    uint32_t a;
    asm("{ .reg .u64 t; cvta.to.shared.u64 t, %1; cvt.u32.u64 %0, t; }" : "=r"(a) : "l"(p));
    return a;
}
#define CP_ASYNC16(dst, src) \
    asm volatile("cp.async.cg.shared.global [%0], [%1], 16;" :: "r"(dst), "l"(src))
#define CP_COMMIT() asm volatile("cp.async.commit_group;" ::: "memory")
#define CP_WAIT(n)  asm volatile("cp.async.wait_group %0;" :: "n"(n) : "memory")
#define SWZ128(b)   ((b) ^ (((b) >> 3) & 0x70))

__device__ __forceinline__ void ldsm_x4(uint32_t& r0, uint32_t& r1, uint32_t& r2,
                                        uint32_t& r3, uint32_t addr) {
    asm volatile("ldmatrix.sync.aligned.m8n8.x4.shared.b16 {%0,%1,%2,%3}, [%4];"
                 : "=r"(r0), "=r"(r1), "=r"(r2), "=r"(r3) : "r"(addr));
}
__device__ __forceinline__ void ldsm_x4t(uint32_t& r0, uint32_t& r1, uint32_t& r2,
                                         uint32_t& r3, uint32_t addr) {
    asm volatile("ldmatrix.sync.aligned.m8n8.x4.trans.shared.b16 {%0,%1,%2,%3}, [%4];"
                 : "=r"(r0), "=r"(r1), "=r"(r2), "=r"(r3) : "r"(addr));
}
__device__ __forceinline__ void mma16816(float* c, const uint32_t* a, const uint32_t* b) {
    asm volatile("mma.sync.aligned.m16n8k16.row.col.f32.f16.f16.f32 "
                 "{%0,%1,%2,%3}, {%4,%5,%6,%7}, {%8,%9}, {%0,%1,%2,%3};"
                 : "+f"(c[0]), "+f"(c[1]), "+f"(c[2]), "+f"(c[3])
                 : "r"(a[0]), "r"(a[1]), "r"(a[2]), "r"(a[3]), "r"(b[0]), "r"(b[1]));
}

// ---------------- quant kernels ---------------------------------------------
__global__ void k_init() {
    int t = threadIdx.x;
    if (t < 128) { g_counts[0][t] = 0; g_counts[1][t] = 0; }
    if (t == 0) {
        g_minkey = 0xFFFFFFFFu; g_maxkey = 0u;
        g_dmax[0] = 0.0f; g_dmax[1] = 0.0f;
    }
}

__global__ void __launch_bounds__(256) k_minmax(const float* __restrict__ U) {
    float lmin = 3.4e38f, lmax = -3.4e38f;
    int stride = gridDim.x * blockDim.x;
    const float4* U4 = (const float4*)U;
    for (int i = blockIdx.x * blockDim.x + threadIdx.x; i < (NROW * DCOLS) / 4; i += stride) {
        float4 v = U4[i];
        lmin = fminf(lmin, fminf(fminf(v.x, v.y), fminf(v.z, v.w)));
        lmax = fmaxf(lmax, fmaxf(fmaxf(v.x, v.y), fmaxf(v.z, v.w)));
    }
#pragma unroll
    for (int o = 16; o; o >>= 1) {
        lmin = fminf(lmin, __shfl_xor_sync(0xffffffffu, lmin, o));
        lmax = fmaxf(lmax, __shfl_xor_sync(0xffffffffu, lmax, o));
    }
    __shared__ float smn[8], smx[8];
    int w = threadIdx.x >> 5;
    if ((threadIdx.x & 31) == 0) { smn[w] = lmin; smx[w] = lmax; }
    __syncthreads();
    if (threadIdx.x == 0) {
        float a = smn[0], b = smx[0];
        for (int q = 1; q < 8; q++) { a = fminf(a, smn[q]); b = fmaxf(b, smx[q]); }
        atomicMin(&g_minkey, fencode(a));
        atomicMax(&g_maxkey, fencode(b));
    }
}

__global__ void k_scales() {
    float mn = fdecode(g_minkey), mx = fdecode(g_maxkey);
    float s0 = __fdiv_rn(mx - mn, 3.0f);
    g_s[0] = s0;
    float s1 = __fdiv_rn(s0, 5.0f);
    g_s[1] = s1;
    g_s[2] = __fdiv_rn(s1, 17.0f);
}

__global__ void __launch_bounds__(256) k_xhalf(const float* __restrict__ x) {
    int v = blockIdx.x * 256 + threadIdx.x;     // float4 index
    float4 a = ((const float4*)x)[v];
    __half2 p0 = __floats2half2_rn(a.x, a.y);
    __half2 p1 = __floats2half2_rn(a.z, a.w);
    uint2 pk;
    pk.x = *reinterpret_cast<uint32_t*>(&p0);
    pk.y = *reinterpret_cast<uint32_t*>(&p1);
    *(uint2*)(&g_xh[(size_t)v * 4]) = pk;
}

__global__ void __launch_bounds__(256) k_deltamax0(const float* __restrict__ U) {
    int j = blockIdx.x * 256 + threadIdx.x;
    float r[8], sv[8];
    load_res_l0(U, j, g_s[0], r);
    sort_vals(r, sv);
    float m = 0.0f;
#pragma unroll
    for (int i = 0; i < 7; i++) m = fmaxf(m, sv[i + 1] - sv[i]);
#pragma unroll
    for (int o = 16; o; o >>= 1) m = fmaxf(m, __shfl_xor_sync(0xffffffffu, m, o));
    __shared__ float sm[8];
    int w = threadIdx.x >> 5;
    if ((threadIdx.x & 31) == 0) sm[w] = m;
    __syncthreads();
    if (threadIdx.x == 0) {
        float mm = sm[0];
        for (int q = 1; q < 8; q++) mm = fmaxf(mm, sm[q]);
        atomicMax((int*)&g_dmax[0], __float_as_int(mm));
    }
}

__global__ void __launch_bounds__(256) k_hist(const float* __restrict__ U,
                                              const float* __restrict__ tm, int lvl) {
    __shared__ int h[128];
    if (threadIdx.x < 128) h[threadIdx.x] = 0;
    __syncthreads();
    int j = blockIdx.x * 256 + threadIdx.x;
    float r[8], sv[8];
    if (lvl == 0) load_res_l0(U, j, g_s[0], r);
    else          load_res_l1(U, j, r);
    sort_vals(r, sv);
    float dmax = g_dmax[lvl];
    float thr  = sigm(tm[j >> 11]);
    atomicAdd(&h[column_code(sv, dmax, thr)], 1);
    __syncthreads();
    if (threadIdx.x < 128 && h[threadIdx.x])
        atomicAdd(&g_counts[lvl][threadIdx.x], h[threadIdx.x]);
}

__global__ void __launch_bounds__(128) k_finalize(const float* __restrict__ U,
                                                  const float* __restrict__ tm, int lvl) {
    __shared__ int cnts[128], rnk[128], tcode[5], trank[5];
    int p = threadIdx.x;
    cnts[p] = g_counts[lvl][p];
    __syncthreads();
    if (p == 0) {
        int r = 0;
        for (int q = 0; q < 128; q++) { rnk[q] = r; if (cnts[q] > 0) r++; }
        bool used[128];
        for (int q = 0; q < 128; q++) used[q] = false;
        for (int t = 0; t < 5; t++) {
            int best = -1, bc = -1;
            for (int q = 0; q < 128; q++)
                if (!used[q] && cnts[q] > bc) { bc = cnts[q]; best = q; }
            used[best] = true;
            tcode[t] = best; trank[t] = rnk[best];
        }
    }
    __syncthreads();
    int bestT = 0, bestV = -1;
#pragma unroll
    for (int t = 0; t < 5; t++) {
        int iv = __popc(p & tcode[t]);
        if (iv > bestV) { bestV = iv; bestT = t; }
    }
    bool istop = false;
#pragma unroll
    for (int t = 0; t < 5; t++) istop |= (rnk[p] == trank[t]);
    g_rank_lut[p] = istop ? rnk[p] : trank[bestT];

    float r[8], sv[8];
    if (lvl == 0) load_res_l0(U, p, g_s[0], r);
    else          load_res_l1(U, p, r);
    sort_vals(r, sv);
    float dmax = g_dmax[lvl];
    float thr  = sigm(tm[p >> 11]);
    unsigned char bits = 0;
#pragma unroll
    for (int i = 0; i < 7; i++) {
        float d  = sv[i + 1] - sv[i];
        float z  = __fdiv_rn(__fdiv_rn(d, dmax) - thr, 0.01f);
        float mv = sigm(z);
        g_msp_tab[i * 128 + p] = mv;
        if ((int)rintf(mv)) bits |= (unsigned char)(1u << i);
    }
    g_rs_tab[p] = bits;
}

// update level lvl; lvl0: writes vsum1 fp32 + fused deltamax1.
// lvl1: writes final W directly as fp16 in natural [e][k][n] layout.
__global__ void __launch_bounds__(256) k_update(const float* __restrict__ U,
                                                const float* __restrict__ tm, int lvl) {
    int j = blockIdx.x * 256 + threadIdx.x;
    float uv[8], vs[8], r[8];
    float s0 = g_s[0];
#pragma unroll
    for (int i = 0; i < 8; i++) {
        uv[i] = U[(size_t)i * DCOLS + j];
        vs[i] = (lvl == 0) ? s0 * ste_floor(__fdiv_rn(uv[i], s0))
                           : g_vsum[(size_t)i * DCOLS + j];
        r[i] = uv[i] - vs[i];
    }
    float sv[8]; int idx[8];
    sort_idx(r, sv, idx);
    float dmax = g_dmax[lvl];
    float thr  = sigm(tm[j >> 11]);
    int code = column_code(sv, dmax, thr);
    int cr = g_rank_lut[code];
    unsigned sb = g_rs_tab[cr];
    float s = g_s[1 + lvl];

    float buf = 0.0f, cnt = 0.0f, g = 1.0f;
    bool reset = false;
    float v[8]; unsigned bl = 0;
#pragma unroll
    for (int i = 0; i < 8; i++) {
        if (reset) { buf = sv[i]; cnt = 1.0f; g = 1.0f; }
        else       { buf += sv[i]; cnt += 1.0f; }
        float mean = __fdiv_rn(buf, cnt);
        if (i == 7) v[7] = g * mean;
        else {
            bool b = (sb >> i) & 1u;
            float mu = g_msp_tab[i * 128 + cr];
            v[i] = b ? (g * mu) * mean : 0.0f;
            if (b) bl |= (1u << i);
            else   g = g * (1.0f - mu);
            reset = b;
        }
    }
    float ro[8];
    float cur = v[7];
    ro[7] = cur;
#pragma unroll
    for (int i = 6; i >= 0; i--) {
        if ((bl >> i) & 1u) cur = v[i];
        ro[i] = cur;
    }
    if (lvl == 0) {
        float nv[8];
#pragma unroll
        for (int i = 0; i < 8; i++) {
            float gi = 0.0f;
#pragma unroll
            for (int k = 0; k < 8; k++) gi = (idx[k] == i) ? ro[k] : gi;
            nv[i] = vs[i] + s * ste_floor(__fdiv_rn(gi, s));
            g_vsum[(size_t)i * DCOLS + j] = nv[i];
        }
        // fused deltamax for level 1
        float r1[8], s1[8];
#pragma unroll
        for (int i = 0; i < 8; i++) r1[i] = uv[i] - nv[i];
        sort_vals(r1, s1);
        float m = 0.0f;
#pragma unroll
        for (int i = 0; i < 7; i++) m = fmaxf(m, s1[i + 1] - s1[i]);
#pragma unroll
        for (int o = 16; o; o >>= 1) m = fmaxf(m, __shfl_xor_sync(0xffffffffu, m, o));
        __shared__ float sm[8];
        int w = threadIdx.x >> 5;
        if ((threadIdx.x & 31) == 0) sm[w] = m;
        __syncthreads();
        if (threadIdx.x == 0) {
            float mm = sm[0];
            for (int q = 1; q < 8; q++) mm = fmaxf(mm, sm[q]);
            atomicMax((int*)&g_dmax[1], __float_as_int(mm));
        }
    } else {
#pragma unroll
        for (int i = 0; i < 8; i++) {
            float gi = 0.0f;
#pragma unroll
            for (int k = 0; k < 8; k++) gi = (idx[k] == i) ? ro[k] : gi;
            float nv = vs[i] + s * ste_floor(__fdiv_rn(gi, s));
            g_wh[(size_t)i * DCOLS + j] = __float2half_rn(nv);
        }
    }
}

// ---------------- HMMA GEMM (single-pass fp16, 3-stage cp.async) ------------
// out[b,e,l] = sum_k x[b,e,k] * w[e,k,l]
// A K-major [m][k] from g_xh; B natural [k][n] from g_wh.
// Stage (32KB): A 16K @0, B 16K @16384. 3 stages = 96KB -> 2 CTAs/SM.
#define GEMM_SMEM (3 * 32768)
#define BSWZ(k, cbyte) ((uint32_t)((k) * 256 + (cbyte)) ^ ((uint32_t)((k) & 7) << 4))

__global__ void __launch_bounds__(256, 2) k_gemm(float* __restrict__ out) {
    extern __shared__ char smemraw[];
    uint32_t smb = smem_u32(smemraw);
    int tid = threadIdx.x, wid = tid >> 5, lane = tid & 31;
    int e = blockIdx.z, bm = blockIdx.y * 128, bn = blockIdx.x * 128;

    const __half* A = g_xh + (size_t)e * 2048  + (size_t)bm * 16384;
    const __half* B = g_wh + (size_t)e * DCOLS + bn;

    // staging address precompute (4 chunks of 16B per thread per stage)
    uint32_t aswz[4], bswz[4];
    size_t aofs[4], bofs[4];
#pragma unroll
    for (int i = 0; i < 4; i++) {
        int v = tid + i * 256;
        int arow = v >> 3, ac = v & 7;          // A: 128 rows x 8 chunks
        aswz[i] = SWZ128((uint32_t)(arow * 128 + ac * 16));
        aofs[i] = (size_t)arow * 16384 + ac * 8;
        int brow = v >> 4, bc = v & 15;         // B: 64 rows x 16 chunks
        bswz[i] = BSWZ(brow, bc * 16);
        bofs[i] = (size_t)brow * 1024 + bc * 8;
    }

    int wm = (wid & 1) * 64, wn = (wid >> 1) * 32;
    int a_row = lane & 15;
    int a_kb  = (lane >> 4) * 16;
    int b_krb = (lane & 7) + ((lane >> 3) & 1) * 8;   // k within 16
    int b_nch = (lane >> 4) * 8;                      // n half within 16

    float c[4][4][4];
#pragma unroll
    for (int mi = 0; mi < 4; mi++)
#pragma unroll
        for (int ni = 0; ni < 4; ni++)
#pragma unroll
            for (int q = 0; q < 4; q++) c[mi][ni][q] = 0.0f;

    // prologue: stages 0, 1
#pragma unroll
    for (int t = 0; t < 2; t++) {
        uint32_t base = smb + t * 32768;
        int k0 = t * 64;
#pragma unroll
        for (int i = 0; i < 4; i++) {
            CP_ASYNC16(base + aswz[i],         A + aofs[i] + k0);
            CP_ASYNC16(base + 16384 + bswz[i], B + bofs[i] + (size_t)k0 * 1024);
        }
        CP_COMMIT();
    }

#pragma unroll 1
    for (int t = 0; t < 32; t++) {
        if (t == 31) { CP_WAIT(0); } else { CP_WAIT(1); }
        __syncthreads();
        if (t + 2 < 32) {
            uint32_t base = smb + ((t + 2) % 3) * 32768;
            int k0 = (t + 2) * 64;
#pragma unroll
            for (int i = 0; i < 4; i++) {
                CP_ASYNC16(base + aswz[i],         A + aofs[i] + k0);
                CP_ASYNC16(base + 16384 + bswz[i], B + bofs[i] + (size_t)k0 * 1024);
            }
            CP_COMMIT();
        }

        uint32_t base = smb + (t % 3) * 32768;
#pragma unroll
        for (int ks = 0; ks < 4; ks++) {
            uint32_t a[4][4], b[4][2];
#pragma unroll
            for (int mi = 0; mi < 4; mi++) {
                int row = wm + mi * 16 + a_row;
                uint32_t off = SWZ128((uint32_t)(row * 128 + ks * 32 + a_kb));
                ldsm_x4(a[mi][0], a[mi][1], a[mi][2], a[mi][3], base + off);
            }
#pragma unroll
            for (int np = 0; np < 2; np++) {
                int k_row = ks * 16 + b_krb;
                int n_col = wn + np * 16 + b_nch;
                uint32_t off = BSWZ(k_row, (n_col >> 3) << 4);
                uint32_t r0, r1, r2, r3;
                ldsm_x4t(r0, r1, r2, r3, base + 16384 + off);
                b[np * 2][0] = r0; b[np * 2][1] = r1;
                b[np * 2 + 1][0] = r2; b[np * 2 + 1][1] = r3;
            }
#pragma unroll
            for (int mi = 0; mi < 4; mi++)
#pragma unroll
                for (int ni = 0; ni < 4; ni++)
                    mma16816(c[mi][ni], a[mi], b[ni]);
        }
    }

    // epilogue
    int group = lane >> 2, tig = lane & 3;
#pragma unroll
    for (int mi = 0; mi < 4; mi++) {
        int m0 = bm + wm + mi * 16 + group;
#pragma unroll
        for (int ni = 0; ni < 4; ni++) {
            int n0 = bn + wn + ni * 8 + tig * 2;
            float2 v0 = make_float2(c[mi][ni][0], c[mi][ni][1]);
            float2 v1 = make_float2(c[mi][ni][2], c[mi][ni][3]);
            *(float2*)(out + (size_t)m0 * 8192 + (size_t)e * 1024 + n0)       = v0;
            *(float2*)(out + (size_t)(m0 + 8) * 8192 + (size_t)e * 1024 + n0) = v1;
        }
    }
}

// ---------------- launch ----------------------------------------------------
extern "C" void kernel_launch(void* const* d_in, const int* in_sizes, int n_in,
                              void* d_out, int out_size) {
    const float* x = nullptr; const float* U = nullptr; const float* tm = nullptr;
    for (int i = 0; i < n_in; i++) {
        if (in_sizes[i] == NROW * DCOLS)      U  = (const float*)d_in[i];
        else if (in_sizes[i] == XELEMS)       x  = (const float*)d_in[i];
        else if (in_sizes[i] == DD2)          tm = (const float*)d_in[i];
    }
    float* out = (float*)d_out;

    cudaFuncSetAttribute(k_gemm, cudaFuncAttributeMaxDynamicSharedMemorySize, GEMM_SMEM);

    k_init<<<1, 256>>>();
    k_minmax<<<2048, 256>>>(U);
    k_scales<<<1, 1>>>();
    k_xhalf<<<XELEMS / 1024, 256>>>(x);

    k_deltamax0<<<DCOLS / 256, 256>>>(U);
    k_hist<<<DCOLS / 256, 256>>>(U, tm, 0);
    k_finalize<<<1, 128>>>(U, tm, 0);
    k_update<<<DCOLS / 256, 256>>>(U, tm, 0);      // writes vsum1, fused deltamax1

    k_hist<<<DCOLS / 256, 256>>>(U, tm, 1);
    k_finalize<<<1, 128>>>(U, tm, 1);
    k_update<<<DCOLS / 256, 256>>>(U, tm, 1);      // writes W fp16 directly

    dim3 gg(DD2 / 128, NBATCH / 128, NROW);
    k_gemm<<<gg, 256, GEMM_SMEM>>>(out);
}

// round 7
// speedup vs baseline: 2.0903x; 1.0053x over previous
#include <cuda_runtime.h>
#include <cuda_fp16.h>
#include <math.h>
#include <stdint.h>

#define NROW   8
#define DCOLS  2097152
#define DD1    2048
#define DD2    1024
#define NBATCH 512
#define XELEMS (NBATCH * NROW * DD1)   // 8388608
#define OUTELEMS (NBATCH * NROW * DD2) // 4194304

// ---------------- scratch (static device globals; no allocations) ----------
__device__ float         g_vsum[NROW * DCOLS];   // 64 MB (vsum1 between levels)
__device__ __half        g_wh[NROW * DCOLS];     // 16 MB  W fp16, natural [e][k][n]
__device__ __half        g_xh[XELEMS];           // 16 MB  x fp16
__device__ unsigned      g_minkey, g_maxkey;
__device__ float         g_s[3];
__device__ float         g_dmax[2];
__device__ int           g_counts[2][128];
__device__ int           g_rank_lut[128];
__device__ float         g_msp_tab[7 * 128];
__device__ unsigned char g_rs_tab[128];

// ---------------- helpers ---------------------------------------------------
__device__ __forceinline__ unsigned fencode(float f) {
    unsigned u = __float_as_uint(f);
    unsigned m = (unsigned)((int)u >> 31);
    return u ^ (m | 0x80000000u);
}
__device__ __forceinline__ float fdecode(unsigned k) {
    unsigned u = (k & 0x80000000u) ? (k ^ 0x80000000u) : ~k;
    return __uint_as_float(u);
}
__device__ __forceinline__ float sigm(float x) {
    return __fdiv_rn(1.0f, 1.0f + expf(-x));
}
__device__ __forceinline__ float ste_floor(float x) {
    return x + (floorf(x) - x);
}

// Batcher 19-CE sorting network for 8 elements
#define SORT8(T, a)                                                     \
    {                                                                   \
        const int P[19][2] = {{0,1},{2,3},{4,5},{6,7},{0,2},{1,3},{4,6},\
            {5,7},{1,2},{5,6},{0,4},{3,7},{1,5},{2,6},{1,4},{3,6},      \
            {2,4},{3,5},{3,4}};                                         \
        _Pragma("unroll")                                               \
        for (int _p = 0; _p < 19; _p++) {                               \
            T _x = a[P[_p][0]], _y = a[P[_p][1]];                       \
            bool _sw = _y < _x;                                         \
            a[P[_p][0]] = _sw ? _y : _x;                                \
            a[P[_p][1]] = _sw ? _x : _y;                                \
        }                                                               \
    }

__device__ __forceinline__ void sort_vals(float r[8], float sv[8]) {
    unsigned k[8];
#pragma unroll
    for (int i = 0; i < 8; i++) k[i] = fencode(r[i]);
    SORT8(unsigned, k);
#pragma unroll
    for (int i = 0; i < 8; i++) sv[i] = fdecode(k[i]);
}
__device__ __forceinline__ void sort_idx(const float r[8], float sv[8], int idx[8]) {
    unsigned long long k[8];
#pragma unroll
    for (int i = 0; i < 8; i++)
        k[i] = ((unsigned long long)fencode(r[i]) << 32) | (unsigned)i;
    SORT8(unsigned long long, k);
#pragma unroll
    for (int i = 0; i < 8; i++) {
        sv[i] = fdecode((unsigned)(k[i] >> 32));
        idx[i] = (int)(k[i] & 7u);
    }
}

__device__ __forceinline__ int column_code(const float sv[8], float dmax, float thr) {
    int code = 0;
#pragma unroll
    for (int i = 0; i < 7; i++) {
        float d  = sv[i + 1] - sv[i];
        float z  = __fdiv_rn(__fdiv_rn(d, dmax) - thr, 0.01f);
        code = (code << 1) | (int)rintf(sigm(z));
    }
    return code;
}
__device__ __forceinline__ float delta_max7(const float sv[8]) {
    float m = 0.0f;
#pragma unroll
    for (int i = 0; i < 7; i++) m = fmaxf(m, sv[i + 1] - sv[i]);
    return m;
}

// ---------------- PTX helpers -------------------------------------------------
__device__ __forceinline__ uint32_t smem_u32(const void* p) {
    uint32_t a;
    asm("{ .reg .u64 t; cvta.to.shared.u64 t, %1; cvt.u32.u64 %0, t; }" : "=r"(a) : "l"(p));
    return a;
}
#define CP_ASYNC16(dst, src) \
    asm volatile("cp.async.cg.shared.global [%0], [%1], 16;" :: "r"(dst), "l"(src))
#define CP_COMMIT() asm volatile("cp.async.commit_group;" ::: "memory")
#define CP_WAIT(n)  asm volatile("cp.async.wait_group %0;" :: "n"(n) : "memory")
#define SWZ128(b)   ((b) ^ (((b) >> 3) & 0x70))

__device__ __forceinline__ void ldsm_x4(uint32_t& r0, uint32_t& r1, uint32_t& r2,
                                        uint32_t& r3, uint32_t addr) {
    asm volatile("ldmatrix.sync.aligned.m8n8.x4.shared.b16 {%0,%1,%2,%3}, [%4];"
                 : "=r"(r0), "=r"(r1), "=r"(r2), "=r"(r3) : "r"(addr));
}
__device__ __forceinline__ void ldsm_x4t(uint32_t& r0, uint32_t& r1, uint32_t& r2,
                                         uint32_t& r3, uint32_t addr) {
    asm volatile("ldmatrix.sync.aligned.m8n8.x4.trans.shared.b16 {%0,%1,%2,%3}, [%4];"
                 : "=r"(r0), "=r"(r1), "=r"(r2), "=r"(r3) : "r"(addr));
}
__device__ __forceinline__ void mma16816(float* c, const uint32_t* a, const uint32_t* b) {
    asm volatile("mma.sync.aligned.m16n8k16.row.col.f32.f16.f16.f32 "
                 "{%0,%1,%2,%3}, {%4,%5,%6,%7}, {%8,%9}, {%0,%1,%2,%3};"
                 : "+f"(c[0]), "+f"(c[1]), "+f"(c[2]), "+f"(c[3])
                 : "r"(a[0]), "r"(a[1]), "r"(a[2]), "r"(a[3]), "r"(b[0]), "r"(b[1]));
}

// ---------------- quant kernels ---------------------------------------------
__global__ void k_init() {
    int t = threadIdx.x;
    if (t < 128) { g_counts[0][t] = 0; g_counts[1][t] = 0; }
    if (t == 0) {
        g_minkey = 0xFFFFFFFFu; g_maxkey = 0u;
        g_dmax[0] = 0.0f; g_dmax[1] = 0.0f;
    }
}

__global__ void __launch_bounds__(256) k_minmax(const float* __restrict__ U) {
    float lmin = 3.4e38f, lmax = -3.4e38f;
    int stride = gridDim.x * blockDim.x;
    const float4* U4 = (const float4*)U;
    for (int i = blockIdx.x * blockDim.x + threadIdx.x; i < (NROW * DCOLS) / 4; i += stride) {
        float4 v = U4[i];
        lmin = fminf(lmin, fminf(fminf(v.x, v.y), fminf(v.z, v.w)));
        lmax = fmaxf(lmax, fmaxf(fmaxf(v.x, v.y), fmaxf(v.z, v.w)));
    }
#pragma unroll
    for (int o = 16; o; o >>= 1) {
        lmin = fminf(lmin, __shfl_xor_sync(0xffffffffu, lmin, o));
        lmax = fmaxf(lmax, __shfl_xor_sync(0xffffffffu, lmax, o));
    }
    __shared__ float smn[8], smx[8];
    int w = threadIdx.x >> 5;
    if ((threadIdx.x & 31) == 0) { smn[w] = lmin; smx[w] = lmax; }
    __syncthreads();
    if (threadIdx.x == 0) {
        float a = smn[0], b = smx[0];
        for (int q = 1; q < 8; q++) { a = fminf(a, smn[q]); b = fmaxf(b, smx[q]); }
        atomicMin(&g_minkey, fencode(a));
        atomicMax(&g_maxkey, fencode(b));
    }
}

__global__ void k_scales() {
    float mn = fdecode(g_minkey), mx = fdecode(g_maxkey);
    float s0 = __fdiv_rn(mx - mn, 3.0f);
    g_s[0] = s0;
    float s1 = __fdiv_rn(s0, 5.0f);
    g_s[1] = s1;
    g_s[2] = __fdiv_rn(s1, 17.0f);
}

__global__ void __launch_bounds__(256) k_xhalf(const float* __restrict__ x) {
    int v0 = (blockIdx.x * 256 + threadIdx.x) * 2;     // two float4 per thread
#pragma unroll
    for (int q = 0; q < 2; q++) {
        int v = v0 + q;
        float4 a = ((const float4*)x)[v];
        __half2 p0 = __floats2half2_rn(a.x, a.y);
        __half2 p1 = __floats2half2_rn(a.z, a.w);
        uint2 pk;
        pk.x = *reinterpret_cast<uint32_t*>(&p0);
        pk.y = *reinterpret_cast<uint32_t*>(&p1);
        *(uint2*)(&g_xh[(size_t)v * 4]) = pk;
    }
}

// level-0 deltamax: 2 columns per thread via float2 loads
__global__ void __launch_bounds__(256) k_deltamax0(const float* __restrict__ U) {
    int j2 = (blockIdx.x * 256 + threadIdx.x) * 2;
    float s0 = g_s[0];
    float ra[8], rb[8];
#pragma unroll
    for (int i = 0; i < 8; i++) {
        float2 u = *(const float2*)&U[(size_t)i * DCOLS + j2];
        ra[i] = u.x - s0 * ste_floor(__fdiv_rn(u.x, s0));
        rb[i] = u.y - s0 * ste_floor(__fdiv_rn(u.y, s0));
    }
    float sa[8], sb[8];
    sort_vals(ra, sa);
    sort_vals(rb, sb);
    float m = fmaxf(delta_max7(sa), delta_max7(sb));
#pragma unroll
    for (int o = 16; o; o >>= 1) m = fmaxf(m, __shfl_xor_sync(0xffffffffu, m, o));
    __shared__ float sm[8];
    int w = threadIdx.x >> 5;
    if ((threadIdx.x & 31) == 0) sm[w] = m;
    __syncthreads();
    if (threadIdx.x == 0) {
        float mm = sm[0];
        for (int q = 1; q < 8; q++) mm = fmaxf(mm, sm[q]);
        atomicMax((int*)&g_dmax[0], __float_as_int(mm));
    }
}

// histogram: 2 columns per thread
__global__ void __launch_bounds__(256) k_hist(const float* __restrict__ U,
                                              const float* __restrict__ tm, int lvl) {
    __shared__ int h[128];
    if (threadIdx.x < 128) h[threadIdx.x] = 0;
    __syncthreads();
    int j2 = (blockIdx.x * 256 + threadIdx.x) * 2;
    float s0 = g_s[0];
    float ra[8], rb[8];
    if (lvl == 0) {
#pragma unroll
        for (int i = 0; i < 8; i++) {
            float2 u = *(const float2*)&U[(size_t)i * DCOLS + j2];
            ra[i] = u.x - s0 * ste_floor(__fdiv_rn(u.x, s0));
            rb[i] = u.y - s0 * ste_floor(__fdiv_rn(u.y, s0));
        }
    } else {
#pragma unroll
        for (int i = 0; i < 8; i++) {
            float2 u = *(const float2*)&U[(size_t)i * DCOLS + j2];
            float2 v = *(const float2*)&g_vsum[(size_t)i * DCOLS + j2];
            ra[i] = u.x - v.x;
            rb[i] = u.y - v.y;
        }
    }
    float sa[8], sb[8];
    sort_vals(ra, sa);
    sort_vals(rb, sb);
    float dmax = g_dmax[lvl];
    float ta = sigm(tm[j2 >> 11]);
    float tb = sigm(tm[(j2 + 1) >> 11]);
    atomicAdd(&h[column_code(sa, dmax, ta)], 1);
    atomicAdd(&h[column_code(sb, dmax, tb)], 1);
    __syncthreads();
    if (threadIdx.x < 128 && h[threadIdx.x])
        atomicAdd(&g_counts[lvl][threadIdx.x], h[threadIdx.x]);
}

__global__ void __launch_bounds__(128) k_finalize(const float* __restrict__ U,
                                                  const float* __restrict__ tm, int lvl) {
    __shared__ int cnts[128], rnk[128], tcode[5], trank[5];
    int p = threadIdx.x;
    cnts[p] = g_counts[lvl][p];
    __syncthreads();
    if (p == 0) {
        int r = 0;
        for (int q = 0; q < 128; q++) { rnk[q] = r; if (cnts[q] > 0) r++; }
        bool used[128];
        for (int q = 0; q < 128; q++) used[q] = false;
        for (int t = 0; t < 5; t++) {
            int best = -1, bc = -1;
            for (int q = 0; q < 128; q++)
                if (!used[q] && cnts[q] > bc) { bc = cnts[q]; best = q; }
            used[best] = true;
            tcode[t] = best; trank[t] = rnk[best];
        }
    }
    __syncthreads();
    int bestT = 0, bestV = -1;
#pragma unroll
    for (int t = 0; t < 5; t++) {
        int iv = __popc(p & tcode[t]);
        if (iv > bestV) { bestV = iv; bestT = t; }
    }
    bool istop = false;
#pragma unroll
    for (int t = 0; t < 5; t++) istop |= (rnk[p] == trank[t]);
    g_rank_lut[p] = istop ? rnk[p] : trank[bestT];

    float r[8], sv[8];
    float s0 = g_s[0];
    if (lvl == 0) {
#pragma unroll
        for (int i = 0; i < 8; i++) {
            float u = U[(size_t)i * DCOLS + p];
            r[i] = u - s0 * ste_floor(__fdiv_rn(u, s0));
        }
    } else {
#pragma unroll
        for (int i = 0; i < 8; i++)
            r[i] = U[(size_t)i * DCOLS + p] - g_vsum[(size_t)i * DCOLS + p];
    }
    sort_vals(r, sv);
    float dmax = g_dmax[lvl];
    float thr  = sigm(tm[p >> 11]);
    unsigned char bits = 0;
#pragma unroll
    for (int i = 0; i < 7; i++) {
        float d  = sv[i + 1] - sv[i];
        float z  = __fdiv_rn(__fdiv_rn(d, dmax) - thr, 0.01f);
        float mv = sigm(z);
        g_msp_tab[i * 128 + p] = mv;
        if ((int)rintf(mv)) bits |= (unsigned char)(1u << i);
    }
    g_rs_tab[p] = bits;
}

// update level lvl; lvl0: writes vsum1 fp32 + fused deltamax1.
// lvl1: writes final W directly as fp16 in natural [e][k][n] layout.
__global__ void __launch_bounds__(256) k_update(const float* __restrict__ U,
                                                const float* __restrict__ tm, int lvl) {
    int j = blockIdx.x * 256 + threadIdx.x;
    float uv[8], vs[8], r[8];
    float s0 = g_s[0];
#pragma unroll
    for (int i = 0; i < 8; i++) {
        uv[i] = U[(size_t)i * DCOLS + j];
        vs[i] = (lvl == 0) ? s0 * ste_floor(__fdiv_rn(uv[i], s0))
                           : g_vsum[(size_t)i * DCOLS + j];
        r[i] = uv[i] - vs[i];
    }
    float sv[8]; int idx[8];
    sort_idx(r, sv, idx);
    float dmax = g_dmax[lvl];
    float thr  = sigm(tm[j >> 11]);
    int code = column_code(sv, dmax, thr);
    int cr = g_rank_lut[code];
    unsigned sb = g_rs_tab[cr];
    float s = g_s[1 + lvl];

    float buf = 0.0f, cnt = 0.0f, g = 1.0f;
    bool reset = false;
    float v[8]; unsigned bl = 0;
#pragma unroll
    for (int i = 0; i < 8; i++) {
        if (reset) { buf = sv[i]; cnt = 1.0f; g = 1.0f; }
        else       { buf += sv[i]; cnt += 1.0f; }
        float mean = __fdiv_rn(buf, cnt);
        if (i == 7) v[7] = g * mean;
        else {
            bool b = (sb >> i) & 1u;
            float mu = g_msp_tab[i * 128 + cr];
            v[i] = b ? (g * mu) * mean : 0.0f;
            if (b) bl |= (1u << i);
            else   g = g * (1.0f - mu);
            reset = b;
        }
    }
    float ro[8];
    float cur = v[7];
    ro[7] = cur;
#pragma unroll
    for (int i = 6; i >= 0; i--) {
        if ((bl >> i) & 1u) cur = v[i];
        ro[i] = cur;
    }
    if (lvl == 0) {
        float nv[8];
#pragma unroll
        for (int i = 0; i < 8; i++) {
            float gi = 0.0f;
#pragma unroll
            for (int k = 0; k < 8; k++) gi = (idx[k] == i) ? ro[k] : gi;
            nv[i] = vs[i] + s * ste_floor(__fdiv_rn(gi, s));
            g_vsum[(size_t)i * DCOLS + j] = nv[i];
        }
        // fused deltamax for level 1
        float r1[8], s1[8];
#pragma unroll
        for (int i = 0; i < 8; i++) r1[i] = uv[i] - nv[i];
        sort_vals(r1, s1);
        float m = delta_max7(s1);
#pragma unroll
        for (int o = 16; o; o >>= 1) m = fmaxf(m, __shfl_xor_sync(0xffffffffu, m, o));
        __shared__ float sm[8];
        int w = threadIdx.x >> 5;
        if ((threadIdx.x & 31) == 0) sm[w] = m;
        __syncthreads();
        if (threadIdx.x == 0) {
            float mm = sm[0];
            for (int q = 1; q < 8; q++) mm = fmaxf(mm, sm[q]);
            atomicMax((int*)&g_dmax[1], __float_as_int(mm));
        }
    } else {
#pragma unroll
        for (int i = 0; i < 8; i++) {
            float gi = 0.0f;
#pragma unroll
            for (int k = 0; k < 8; k++) gi = (idx[k] == i) ? ro[k] : gi;
            float nv = vs[i] + s * ste_floor(__fdiv_rn(gi, s));
            g_wh[(size_t)i * DCOLS + j] = __float2half_rn(nv);
        }
    }
}

__global__ void __launch_bounds__(256) k_zero(float* __restrict__ out) {
    int i = blockIdx.x * 256 + threadIdx.x;
    ((float4*)out)[i] = make_float4(0.f, 0.f, 0.f, 0.f);
}

// ---------------- HMMA GEMM (fp16, split-K x2, 3-stage cp.async) ------------
// out[b,e,l] += sum_{k in half kz} x[b,e,k] * w[e,k,l]
// grid: (DD2/128, NBATCH/128, NROW*2); z = e*2 + kz
#define GEMM_SMEM (3 * 32768)
#define BSWZ(k, cbyte) ((uint32_t)((k) * 256 + (cbyte)) ^ ((uint32_t)((k) & 7) << 4))
#define KTILES 16

__global__ void __launch_bounds__(256, 2) k_gemm(float* __restrict__ out) {
    extern __shared__ char smemraw[];
    uint32_t smb = smem_u32(smemraw);
    int tid = threadIdx.x, wid = tid >> 5, lane = tid & 31;
    int e = blockIdx.z >> 1, kz = blockIdx.z & 1;
    int bm = blockIdx.y * 128, bn = blockIdx.x * 128;
    int kbase = kz * 1024;

    const __half* A = g_xh + (size_t)e * 2048  + (size_t)bm * 16384 + kbase;
    const __half* B = g_wh + (size_t)e * DCOLS + (size_t)kbase * 1024 + bn;

    uint32_t aswz[4], bswz[4];
    size_t aofs[4], bofs[4];
#pragma unroll
    for (int i = 0; i < 4; i++) {
        int v = tid + i * 256;
        int arow = v >> 3, ac = v & 7;
        aswz[i] = SWZ128((uint32_t)(arow * 128 + ac * 16));
        aofs[i] = (size_t)arow * 16384 + ac * 8;
        int brow = v >> 4, bc = v & 15;
        bswz[i] = BSWZ(brow, bc * 16);
        bofs[i] = (size_t)brow * 1024 + bc * 8;
    }

    int wm = (wid & 1) * 64, wn = (wid >> 1) * 32;
    int a_row = lane & 15;
    int a_kb  = (lane >> 4) * 16;
    int b_krb = (lane & 7) + ((lane >> 3) & 1) * 8;
    int b_nch = (lane >> 4) * 8;

    float c[4][4][4];
#pragma unroll
    for (int mi = 0; mi < 4; mi++)
#pragma unroll
        for (int ni = 0; ni < 4; ni++)
#pragma unroll
            for (int q = 0; q < 4; q++) c[mi][ni][q] = 0.0f;

#pragma unroll
    for (int t = 0; t < 2; t++) {
        uint32_t base = smb + t * 32768;
        int k0 = t * 64;
#pragma unroll
        for (int i = 0; i < 4; i++) {
            CP_ASYNC16(base + aswz[i],         A + aofs[i] + k0);
            CP_ASYNC16(base + 16384 + bswz[i], B + bofs[i] + (size_t)k0 * 1024);
        }
        CP_COMMIT();
    }

#pragma unroll 1
    for (int t = 0; t < KTILES; t++) {
        if (t == KTILES - 1) { CP_WAIT(0); } else { CP_WAIT(1); }
        __syncthreads();
        if (t + 2 < KTILES) {
            uint32_t base = smb + ((t + 2) % 3) * 32768;
            int k0 = (t + 2) * 64;
#pragma unroll
            for (int i = 0; i < 4; i++) {
                CP_ASYNC16(base + aswz[i],         A + aofs[i] + k0);
                CP_ASYNC16(base + 16384 + bswz[i], B + bofs[i] + (size_t)k0 * 1024);
            }
            CP_COMMIT();
        }

        uint32_t base = smb + (t % 3) * 32768;
#pragma unroll
        for (int ks = 0; ks < 4; ks++) {
            uint32_t a[4][4], b[4][2];
#pragma unroll
            for (int mi = 0; mi < 4; mi++) {
                int row = wm + mi * 16 + a_row;
                uint32_t off = SWZ128((uint32_t)(row * 128 + ks * 32 + a_kb));
                ldsm_x4(a[mi][0], a[mi][1], a[mi][2], a[mi][3], base + off);
            }
#pragma unroll
            for (int np = 0; np < 2; np++) {
                int k_row = ks * 16 + b_krb;
                int n_col = wn + np * 16 + b_nch;
                uint32_t off = BSWZ(k_row, (n_col >> 3) << 4);
                uint32_t r0, r1, r2, r3;
                ldsm_x4t(r0, r1, r2, r3, base + 16384 + off);
                b[np * 2][0] = r0; b[np * 2][1] = r1;
                b[np * 2 + 1][0] = r2; b[np * 2 + 1][1] = r3;
            }
#pragma unroll
            for (int mi = 0; mi < 4; mi++)
#pragma unroll
                for (int ni = 0; ni < 4; ni++)
                    mma16816(c[mi][ni], a[mi], b[ni]);
        }
    }

    // epilogue: atomic accumulate the K-split partials
    int group = lane >> 2, tig = lane & 3;
#pragma unroll
    for (int mi = 0; mi < 4; mi++) {
        int m0 = bm + wm + mi * 16 + group;
#pragma unroll
        for (int ni = 0; ni < 4; ni++) {
            int n0 = bn + wn + ni * 8 + tig * 2;
            float* p0 = out + (size_t)m0 * 8192 + (size_t)e * 1024 + n0;
            float* p1 = out + (size_t)(m0 + 8) * 8192 + (size_t)e * 1024 + n0;
            atomicAdd(p0,     c[mi][ni][0]);
            atomicAdd(p0 + 1, c[mi][ni][1]);
            atomicAdd(p1,     c[mi][ni][2]);
            atomicAdd(p1 + 1, c[mi][ni][3]);
        }
    }
}

// ---------------- launch ----------------------------------------------------
extern "C" void kernel_launch(void* const* d_in, const int* in_sizes, int n_in,
                              void* d_out, int out_size) {
    const float* x = nullptr; const float* U = nullptr; const float* tm = nullptr;
    for (int i = 0; i < n_in; i++) {
        if (in_sizes[i] == NROW * DCOLS)      U  = (const float*)d_in[i];
        else if (in_sizes[i] == XELEMS)       x  = (const float*)d_in[i];
        else if (in_sizes[i] == DD2)          tm = (const float*)d_in[i];
    }
    float* out = (float*)d_out;

    cudaFuncSetAttribute(k_gemm, cudaFuncAttributeMaxDynamicSharedMemorySize, GEMM_SMEM);

    k_init<<<1, 256>>>();
    k_minmax<<<2048, 256>>>(U);
    k_scales<<<1, 1>>>();
    k_xhalf<<<XELEMS / 2048, 256>>>(x);
    k_zero<<<OUTELEMS / 1024, 256>>>(out);

    k_deltamax0<<<DCOLS / 512, 256>>>(U);
    k_hist<<<DCOLS / 512, 256>>>(U, tm, 0);
    k_finalize<<<1, 128>>>(U, tm, 0);
    k_update<<<DCOLS / 256, 256>>>(U, tm, 0);      // writes vsum1, fused deltamax1

    k_hist<<<DCOLS / 512, 256>>>(U, tm, 1);
    k_finalize<<<1, 128>>>(U, tm, 1);
    k_update<<<DCOLS / 256, 256>>>(U, tm, 1);      // writes W fp16 directly

    dim3 gg(DD2 / 128, NBATCH / 128, NROW * 2);
    k_gemm<<<gg, 256, GEMM_SMEM>>>(out);
}

// round 8
// speedup vs baseline: 3.0208x; 1.4452x over previous
#include <cuda_runtime.h>
#include <cuda_fp16.h>
#include <math.h>
#include <stdint.h>

#define NROW   8
#define DCOLS  2097152
#define DD1    2048
#define DD2    1024
#define NBATCH 512
#define XELEMS (NBATCH * NROW * DD1)   // 8388608

// ---------------- scratch (static device globals; no allocations) ----------
__device__ float         g_res[NROW * DCOLS];    // 64 MB: r1 = U - vsum1 after update0
__device__ __half        g_wh[NROW * DCOLS];     // 16 MB  W fp16, natural [e][k][n]
__device__ __half        g_xh[XELEMS];           // 16 MB  x fp16
__device__ unsigned      g_minkey, g_maxkey;
__device__ float         g_s[3];                 // s0, s1, s2
__device__ float         g_sinv[3];              // 1/s0, 1/s1, 1/s2
__device__ float         g_thr[1024];            // sigm(thres_mean)
__device__ float         g_dmax[2];
__device__ int           g_counts[2][128];
__device__ int           g_rank_lut[128];
__device__ float         g_msp_tab[7 * 128];
__device__ unsigned char g_rs_tab[128];

// ---------------- helpers ---------------------------------------------------
__device__ __forceinline__ unsigned fencode(float f) {
    unsigned u = __float_as_uint(f);
    unsigned m = (unsigned)((int)u >> 31);
    return u ^ (m | 0x80000000u);
}
__device__ __forceinline__ float fdecode(unsigned k) {
    unsigned u = (k & 0x80000000u) ? (k ^ 0x80000000u) : ~k;
    return __uint_as_float(u);
}
__device__ __forceinline__ float sigm(float x) {
    return __fdiv_rn(1.0f, 1.0f + expf(-x));
}

// Batcher 19-CE sorting network for 8 elements
#define SORT8(T, a)                                                     \
    {                                                                   \
        const int P[19][2] = {{0,1},{2,3},{4,5},{6,7},{0,2},{1,3},{4,6},\
            {5,7},{1,2},{5,6},{0,4},{3,7},{1,5},{2,6},{1,4},{3,6},      \
            {2,4},{3,5},{3,4}};                                         \
        _Pragma("unroll")                                               \
        for (int _p = 0; _p < 19; _p++) {                               \
            T _x = a[P[_p][0]], _y = a[P[_p][1]];                       \
            bool _sw = _y < _x;                                         \
            a[P[_p][0]] = _sw ? _y : _x;                                \
            a[P[_p][1]] = _sw ? _x : _y;                                \
        }                                                               \
    }

__device__ __forceinline__ void sort_vals(float r[8], float sv[8]) {
    unsigned k[8];
#pragma unroll
    for (int i = 0; i < 8; i++) k[i] = fencode(r[i]);
    SORT8(unsigned, k);
#pragma unroll
    for (int i = 0; i < 8; i++) sv[i] = fdecode(k[i]);
}
__device__ __forceinline__ void sort_idx(const float r[8], float sv[8], int idx[8]) {
    unsigned long long k[8];
#pragma unroll
    for (int i = 0; i < 8; i++)
        k[i] = ((unsigned long long)fencode(r[i]) << 32) | (unsigned)i;
    SORT8(unsigned long long, k);
#pragma unroll
    for (int i = 0; i < 8; i++) {
        sv[i] = fdecode((unsigned)(k[i] >> 32));
        idx[i] = (int)(k[i] & 7u);
    }
}

// code bit i = (sigmoid((d/dmax - thr)/0.01) rounds to 1) == (d > thr*dmax)
__device__ __forceinline__ int column_code_fast(const float sv[8], float thr_dmax) {
    int code = 0;
#pragma unroll
    for (int i = 0; i < 7; i++)
        code = (code << 1) | ((sv[i + 1] - sv[i]) > thr_dmax ? 1 : 0);
    return code;
}
__device__ __forceinline__ float delta_max7(const float sv[8]) {
    float m = 0.0f;
#pragma unroll
    for (int i = 0; i < 7; i++) m = fmaxf(m, sv[i + 1] - sv[i]);
    return m;
}

// ---------------- PTX helpers -------------------------------------------------
__device__ __forceinline__ uint32_t smem_u32(const void* p) {
    uint32_t a;
    asm("{ .reg .u64 t; cvta.to.shared.u64 t, %1; cvt.u32.u64 %0, t; }" : "=r"(a) : "l"(p));
    return a;
}
#define CP_ASYNC16(dst, src) \
    asm volatile("cp.async.cg.shared.global [%0], [%1], 16;" :: "r"(dst), "l"(src))
#define CP_COMMIT() asm volatile("cp.async.commit_group;" ::: "memory")
#define CP_WAIT(n)  asm volatile("cp.async.wait_group %0;" :: "n"(n) : "memory")
#define SWZ128(b)   ((b) ^ (((b) >> 3) & 0x70))

__device__ __forceinline__ void ldsm_x4(uint32_t& r0, uint32_t& r1, uint32_t& r2,
                                        uint32_t& r3, uint32_t addr) {
    asm volatile("ldmatrix.sync.aligned.m8n8.x4.shared.b16 {%0,%1,%2,%3}, [%4];"
                 : "=r"(r0), "=r"(r1), "=r"(r2), "=r"(r3) : "r"(addr));
}
__device__ __forceinline__ void ldsm_x4t(uint32_t& r0, uint32_t& r1, uint32_t& r2,
                                         uint32_t& r3, uint32_t addr) {
    asm volatile("ldmatrix.sync.aligned.m8n8.x4.trans.shared.b16 {%0,%1,%2,%3}, [%4];"
                 : "=r"(r0), "=r"(r1), "=r"(r2), "=r"(r3) : "r"(addr));
}
__device__ __forceinline__ void mma16816(float* c, const uint32_t* a, const uint32_t* b) {
    asm volatile("mma.sync.aligned.m16n8k16.row.col.f32.f16.f16.f32 "
                 "{%0,%1,%2,%3}, {%4,%5,%6,%7}, {%8,%9}, {%0,%1,%2,%3};"
                 : "+f"(c[0]), "+f"(c[1]), "+f"(c[2]), "+f"(c[3])
                 : "r"(a[0]), "r"(a[1]), "r"(a[2]), "r"(a[3]), "r"(b[0]), "r"(b[1]));
}

// ---------------- quant kernels ---------------------------------------------
__global__ void k_init() {
    int t = threadIdx.x;
    if (t < 128) { g_counts[0][t] = 0; g_counts[1][t] = 0; }
    if (t == 0) {
        g_minkey = 0xFFFFFFFFu; g_maxkey = 0u;
        g_dmax[0] = 0.0f; g_dmax[1] = 0.0f;
    }
}

__global__ void __launch_bounds__(256) k_minmax(const float* __restrict__ U) {
    float lmin = 3.4e38f, lmax = -3.4e38f;
    int stride = gridDim.x * blockDim.x;
    const float4* U4 = (const float4*)U;
    for (int i = blockIdx.x * blockDim.x + threadIdx.x; i < (NROW * DCOLS) / 4; i += stride) {
        float4 v = U4[i];
        lmin = fminf(lmin, fminf(fminf(v.x, v.y), fminf(v.z, v.w)));
        lmax = fmaxf(lmax, fmaxf(fmaxf(v.x, v.y), fmaxf(v.z, v.w)));
    }
#pragma unroll
    for (int o = 16; o; o >>= 1) {
        lmin = fminf(lmin, __shfl_xor_sync(0xffffffffu, lmin, o));
        lmax = fmaxf(lmax, __shfl_xor_sync(0xffffffffu, lmax, o));
    }
    __shared__ float smn[8], smx[8];
    int w = threadIdx.x >> 5;
    if ((threadIdx.x & 31) == 0) { smn[w] = lmin; smx[w] = lmax; }
    __syncthreads();
    if (threadIdx.x == 0) {
        float a = smn[0], b = smx[0];
        for (int q = 1; q < 8; q++) { a = fminf(a, smn[q]); b = fmaxf(b, smx[q]); }
        atomicMin(&g_minkey, fencode(a));
        atomicMax(&g_maxkey, fencode(b));
    }
}

// scales + thr table (sigm of thres_mean, broadcast to all passes)
__global__ void __launch_bounds__(256) k_scales(const float* __restrict__ tm) {
    int t = blockIdx.x * 256 + threadIdx.x;
    if (t < 1024) g_thr[t] = sigm(tm[t]);
    if (t == 0) {
        float mn = fdecode(g_minkey), mx = fdecode(g_maxkey);
        float s0 = __fdiv_rn(mx - mn, 3.0f);
        float s1 = __fdiv_rn(s0, 5.0f);
        float s2 = __fdiv_rn(s1, 17.0f);
        g_s[0] = s0; g_s[1] = s1; g_s[2] = s2;
        g_sinv[0] = __fdiv_rn(1.0f, s0);
        g_sinv[1] = __fdiv_rn(1.0f, s1);
        g_sinv[2] = __fdiv_rn(1.0f, s2);
    }
}

__global__ void __launch_bounds__(256) k_xhalf(const float* __restrict__ x) {
    int v0 = (blockIdx.x * 256 + threadIdx.x) * 2;
#pragma unroll
    for (int q = 0; q < 2; q++) {
        int v = v0 + q;
        float4 a = ((const float4*)x)[v];
        __half2 p0 = __floats2half2_rn(a.x, a.y);
        __half2 p1 = __floats2half2_rn(a.z, a.w);
        uint2 pk;
        pk.x = *reinterpret_cast<uint32_t*>(&p0);
        pk.y = *reinterpret_cast<uint32_t*>(&p1);
        *(uint2*)(&g_xh[(size_t)v * 4]) = pk;
    }
}

__global__ void __launch_bounds__(256) k_deltamax0(const float* __restrict__ U) {
    int j2 = (blockIdx.x * 256 + threadIdx.x) * 2;
    float s0 = g_s[0], is0 = g_sinv[0];
    float ra[8], rb[8];
#pragma unroll
    for (int i = 0; i < 8; i++) {
        float2 u = *(const float2*)&U[(size_t)i * DCOLS + j2];
        ra[i] = u.x - s0 * floorf(u.x * is0);
        rb[i] = u.y - s0 * floorf(u.y * is0);
    }
    float sa[8], sb[8];
    sort_vals(ra, sa);
    sort_vals(rb, sb);
    float m = fmaxf(delta_max7(sa), delta_max7(sb));
#pragma unroll
    for (int o = 16; o; o >>= 1) m = fmaxf(m, __shfl_xor_sync(0xffffffffu, m, o));
    __shared__ float sm[8];
    int w = threadIdx.x >> 5;
    if ((threadIdx.x & 31) == 0) sm[w] = m;
    __syncthreads();
    if (threadIdx.x == 0) {
        float mm = sm[0];
        for (int q = 1; q < 8; q++) mm = fmaxf(mm, sm[q]);
        atomicMax((int*)&g_dmax[0], __float_as_int(mm));
    }
}

// histogram: 2 columns per thread; lvl1 reads stored r1 directly (64MB not 128MB)
__global__ void __launch_bounds__(256) k_hist(const float* __restrict__ U, int lvl) {
    __shared__ int h[128];
    if (threadIdx.x < 128) h[threadIdx.x] = 0;
    __syncthreads();
    int j2 = (blockIdx.x * 256 + threadIdx.x) * 2;
    float ra[8], rb[8];
    if (lvl == 0) {
        float s0 = g_s[0], is0 = g_sinv[0];
#pragma unroll
        for (int i = 0; i < 8; i++) {
            float2 u = *(const float2*)&U[(size_t)i * DCOLS + j2];
            ra[i] = u.x - s0 * floorf(u.x * is0);
            rb[i] = u.y - s0 * floorf(u.y * is0);
        }
    } else {
#pragma unroll
        for (int i = 0; i < 8; i++) {
            float2 r = *(const float2*)&g_res[(size_t)i * DCOLS + j2];
            ra[i] = r.x; rb[i] = r.y;
        }
    }
    float sa[8], sb[8];
    sort_vals(ra, sa);
    sort_vals(rb, sb);
    float dmax = g_dmax[lvl];
    float tda = g_thr[j2 >> 11] * dmax;
    float tdb = g_thr[(j2 + 1) >> 11] * dmax;
    atomicAdd(&h[column_code_fast(sa, tda)], 1);
    atomicAdd(&h[column_code_fast(sb, tdb)], 1);
    __syncthreads();
    if (threadIdx.x < 128 && h[threadIdx.x])
        atomicAdd(&g_counts[lvl][threadIdx.x], h[threadIdx.x]);
}

__global__ void __launch_bounds__(128) k_finalize(const float* __restrict__ U, int lvl) {
    __shared__ int cnts[128], rnk[128], tcode[5], trank[5];
    int p = threadIdx.x;
    cnts[p] = g_counts[lvl][p];
    __syncthreads();
    if (p == 0) {
        int r = 0;
        for (int q = 0; q < 128; q++) { rnk[q] = r; if (cnts[q] > 0) r++; }
        bool used[128];
        for (int q = 0; q < 128; q++) used[q] = false;
        for (int t = 0; t < 5; t++) {
            int best = -1, bc = -1;
            for (int q = 0; q < 128; q++)
                if (!used[q] && cnts[q] > bc) { bc = cnts[q]; best = q; }
            used[best] = true;
            tcode[t] = best; trank[t] = rnk[best];
        }
    }
    __syncthreads();
    int bestT = 0, bestV = -1;
#pragma unroll
    for (int t = 0; t < 5; t++) {
        int iv = __popc(p & tcode[t]);
        if (iv > bestV) { bestV = iv; bestT = t; }
    }
    bool istop = false;
#pragma unroll
    for (int t = 0; t < 5; t++) istop |= (rnk[p] == trank[t]);
    g_rank_lut[p] = istop ? rnk[p] : trank[bestT];

    // msp / rs table for data columns 0..127 (exact math; 128 threads only)
    float r[8], sv[8];
    if (lvl == 0) {
        float s0 = g_s[0], is0 = g_sinv[0];
#pragma unroll
        for (int i = 0; i < 8; i++) {
            float u = U[(size_t)i * DCOLS + p];
            r[i] = u - s0 * floorf(u * is0);
        }
    } else {
#pragma unroll
        for (int i = 0; i < 8; i++)
            r[i] = g_res[(size_t)i * DCOLS + p];
    }
    sort_vals(r, sv);
    float dmax = g_dmax[lvl];
    float thr  = g_thr[p >> 11];
    unsigned char bits = 0;
#pragma unroll
    for (int i = 0; i < 7; i++) {
        float d  = sv[i + 1] - sv[i];
        float z  = __fdiv_rn(__fdiv_rn(d, dmax) - thr, 0.01f);
        float mv = sigm(z);
        g_msp_tab[i * 128 + p] = mv;
        if ((int)rintf(mv)) bits |= (unsigned char)(1u << i);
    }
    g_rs_tab[p] = bits;
}

// update lvl0: computes vsum1, stores r1 = U - vsum1, fused deltamax1.
// update lvl1: reads r1 + U, writes final W fp16.
__global__ void __launch_bounds__(256) k_update(const float* __restrict__ U, int lvl) {
    int j = blockIdx.x * 256 + threadIdx.x;
    float uv[8], vs[8], r[8];
    if (lvl == 0) {
        float s0 = g_s[0], is0 = g_sinv[0];
#pragma unroll
        for (int i = 0; i < 8; i++) {
            uv[i] = U[(size_t)i * DCOLS + j];
            vs[i] = s0 * floorf(uv[i] * is0);
            r[i] = uv[i] - vs[i];
        }
    } else {
#pragma unroll
        for (int i = 0; i < 8; i++) {
            uv[i] = U[(size_t)i * DCOLS + j];
            r[i] = g_res[(size_t)i * DCOLS + j];
            vs[i] = uv[i] - r[i];
        }
    }
    float sv[8]; int idx[8];
    sort_idx(r, sv, idx);
    float dmax = g_dmax[lvl];
    float td = g_thr[j >> 11] * dmax;
    int code = column_code_fast(sv, td);
    int cr = g_rank_lut[code];
    unsigned sb = g_rs_tab[cr];
    float s = g_s[1 + lvl], is = g_sinv[1 + lvl];

    float buf = 0.0f, cnt = 0.0f, g = 1.0f;
    bool reset = false;
    float v[8]; unsigned bl = 0;
#pragma unroll
    for (int i = 0; i < 8; i++) {
        if (reset) { buf = sv[i]; cnt = 1.0f; g = 1.0f; }
        else       { buf += sv[i]; cnt += 1.0f; }
        float mean = __fdividef(buf, cnt);
        if (i == 7) v[7] = g * mean;
        else {
            bool b = (sb >> i) & 1u;
            float mu = g_msp_tab[i * 128 + cr];
            v[i] = b ? (g * mu) * mean : 0.0f;
            if (b) bl |= (1u << i);
            else   g = g * (1.0f - mu);
            reset = b;
        }
    }
    float ro[8];
    float cur = v[7];
    ro[7] = cur;
#pragma unroll
    for (int i = 6; i >= 0; i--) {
        if ((bl >> i) & 1u) cur = v[i];
        ro[i] = cur;
    }
    if (lvl == 0) {
#pragma unroll
        for (int i = 0; i < 8; i++) {
            float gi = 0.0f;
#pragma unroll
            for (int k = 0; k < 8; k++) gi = (idx[k] == i) ? ro[k] : gi;
            float nv = vs[i] + s * floorf(gi * is);
            r[i] = uv[i] - nv;                        // r1
            g_res[(size_t)i * DCOLS + j] = r[i];
        }
        // fused deltamax for level 1 on stored r1
        float s1[8];
        sort_vals(r, s1);
        float m = delta_max7(s1);
#pragma unroll
        for (int o = 16; o; o >>= 1) m = fmaxf(m, __shfl_xor_sync(0xffffffffu, m, o));
        __shared__ float sm[8];
        int w = threadIdx.x >> 5;
        if ((threadIdx.x & 31) == 0) sm[w] = m;
        __syncthreads();
        if (threadIdx.x == 0) {
            float mm = sm[0];
            for (int q = 1; q < 8; q++) mm = fmaxf(mm, sm[q]);
            atomicMax((int*)&g_dmax[1], __float_as_int(mm));
        }
    } else {
#pragma unroll
        for (int i = 0; i < 8; i++) {
            float gi = 0.0f;
#pragma unroll
            for (int k = 0; k < 8; k++) gi = (idx[k] == i) ? ro[k] : gi;
            float nv = vs[i] + s * floorf(gi * is);
            g_wh[(size_t)i * DCOLS + j] = __float2half_rn(nv);
        }
    }
}

// ---------------- HMMA GEMM (fp16, full-K, 3-stage cp.async) ----------------
#define GEMM_SMEM (3 * 32768)
#define BSWZ(k, cbyte) ((uint32_t)((k) * 256 + (cbyte)) ^ ((uint32_t)((k) & 7) << 4))
#define KTILES 32

__global__ void __launch_bounds__(256, 2) k_gemm(float* __restrict__ out) {
    extern __shared__ char smemraw[];
    uint32_t smb = smem_u32(smemraw);
    int tid = threadIdx.x, wid = tid >> 5, lane = tid & 31;
    int e = blockIdx.z, bm = blockIdx.y * 128, bn = blockIdx.x * 128;

    const __half* A = g_xh + (size_t)e * 2048  + (size_t)bm * 16384;
    const __half* B = g_wh + (size_t)e * DCOLS + bn;

    uint32_t aswz[4], bswz[4];
    size_t aofs[4], bofs[4];
#pragma unroll
    for (int i = 0; i < 4; i++) {
        int v = tid + i * 256;
        int arow = v >> 3, ac = v & 7;
        aswz[i] = SWZ128((uint32_t)(arow * 128 + ac * 16));
        aofs[i] = (size_t)arow * 16384 + ac * 8;
        int brow = v >> 4, bc = v & 15;
        bswz[i] = BSWZ(brow, bc * 16);
        bofs[i] = (size_t)brow * 1024 + bc * 8;
    }

    int wm = (wid & 1) * 64, wn = (wid >> 1) * 32;
    int a_row = lane & 15;
    int a_kb  = (lane >> 4) * 16;
    int b_krb = (lane & 7) + ((lane >> 3) & 1) * 8;
    int b_nch = (lane >> 4) * 8;

    float c[4][4][4];
#pragma unroll
    for (int mi = 0; mi < 4; mi++)
#pragma unroll
        for (int ni = 0; ni < 4; ni++)
#pragma unroll
            for (int q = 0; q < 4; q++) c[mi][ni][q] = 0.0f;

#pragma unroll
    for (int t = 0; t < 2; t++) {
        uint32_t base = smb + t * 32768;
        int k0 = t * 64;
#pragma unroll
        for (int i = 0; i < 4; i++) {
            CP_ASYNC16(base + aswz[i],         A + aofs[i] + k0);
            CP_ASYNC16(base + 16384 + bswz[i], B + bofs[i] + (size_t)k0 * 1024);
        }
        CP_COMMIT();
    }

#pragma unroll 1
    for (int t = 0; t < KTILES; t++) {
        if (t == KTILES - 1) { CP_WAIT(0); } else { CP_WAIT(1); }
        __syncthreads();
        if (t + 2 < KTILES) {
            uint32_t base = smb + ((t + 2) % 3) * 32768;
            int k0 = (t + 2) * 64;
#pragma unroll
            for (int i = 0; i < 4; i++) {
                CP_ASYNC16(base + aswz[i],         A + aofs[i] + k0);
                CP_ASYNC16(base + 16384 + bswz[i], B + bofs[i] + (size_t)k0 * 1024);
            }
            CP_COMMIT();
        }

        uint32_t base = smb + (t % 3) * 32768;
#pragma unroll
        for (int ks = 0; ks < 4; ks++) {
            uint32_t a[4][4], b[4][2];
#pragma unroll
            for (int mi = 0; mi < 4; mi++) {
                int row = wm + mi * 16 + a_row;
                uint32_t off = SWZ128((uint32_t)(row * 128 + ks * 32 + a_kb));
                ldsm_x4(a[mi][0], a[mi][1], a[mi][2], a[mi][3], base + off);
            }
#pragma unroll
            for (int np = 0; np < 2; np++) {
                int k_row = ks * 16 + b_krb;
                int n_col = wn + np * 16 + b_nch;
                uint32_t off = BSWZ(k_row, (n_col >> 3) << 4);
                uint32_t r0, r1, r2, r3;
                ldsm_x4t(r0, r1, r2, r3, base + 16384 + off);
                b[np * 2][0] = r0; b[np * 2][1] = r1;
                b[np * 2 + 1][0] = r2; b[np * 2 + 1][1] = r3;
            }
#pragma unroll
            for (int mi = 0; mi < 4; mi++)
#pragma unroll
                for (int ni = 0; ni < 4; ni++)
                    mma16816(c[mi][ni], a[mi], b[ni]);
        }
    }

    int group = lane >> 2, tig = lane & 3;
#pragma unroll
    for (int mi = 0; mi < 4; mi++) {
        int m0 = bm + wm + mi * 16 + group;
#pragma unroll
        for (int ni = 0; ni < 4; ni++) {
            int n0 = bn + wn + ni * 8 + tig * 2;
            float2 v0 = make_float2(c[mi][ni][0], c[mi][ni][1]);
            float2 v1 = make_float2(c[mi][ni][2], c[mi][ni][3]);
            *(float2*)(out + (size_t)m0 * 8192 + (size_t)e * 1024 + n0)       = v0;
            *(float2*)(out + (size_t)(m0 + 8) * 8192 + (size_t)e * 1024 + n0) = v1;
        }
    }
}

// ---------------- launch ----------------------------------------------------
extern "C" void kernel_launch(void* const* d_in, const int* in_sizes, int n_in,
                              void* d_out, int out_size) {
    const float* x = nullptr; const float* U = nullptr; const float* tm = nullptr;
    for (int i = 0; i < n_in; i++) {
        if (in_sizes[i] == NROW * DCOLS)      U  = (const float*)d_in[i];
        else if (in_sizes[i] == XELEMS)       x  = (const float*)d_in[i];
        else if (in_sizes[i] == DD2)          tm = (const float*)d_in[i];
    }
    float* out = (float*)d_out;

    cudaFuncSetAttribute(k_gemm, cudaFuncAttributeMaxDynamicSharedMemorySize, GEMM_SMEM);

    k_init<<<1, 256>>>();
    k_minmax<<<2048, 256>>>(U);
    k_scales<<<4, 256>>>(tm);
    k_xhalf<<<XELEMS / 2048, 256>>>(x);

    k_deltamax0<<<DCOLS / 512, 256>>>(U);
    k_hist<<<DCOLS / 512, 256>>>(U, 0);
    k_finalize<<<1, 128>>>(U, 0);
    k_update<<<DCOLS / 256, 256>>>(U, 0);      // stores r1, fused deltamax1

    k_hist<<<DCOLS / 512, 256>>>(U, 1);
    k_finalize<<<1, 128>>>(U, 1);
    k_update<<<DCOLS / 256, 256>>>(U, 1);      // writes W fp16 directly

    dim3 gg(DD2 / 128, NBATCH / 128, NROW);
    k_gemm<<<gg, 256, GEMM_SMEM>>>(out);
}